// round 6
// baseline (speedup 1.0000x reference)
#include <cuda_runtime.h>
#include <cuda_bf16.h>
#include <cstdint>

#define NN_NODES 100000
#define EE_EDGES 300000
#define EMB 256
#define NUM_LAYER 5
#define BN_EPS 1e-5f

static inline int cdiv(int a, int b) { return (a + b - 1) / b; }

// ----------------------------------------------------------------------------
// Device scratch (no allocations allowed). Symbols only referenced from device
// code (host-side use would take the shadow symbol's address).
// ----------------------------------------------------------------------------
__device__ float g_h   [(size_t)NN_NODES * EMB];       // node features (layer input)
__device__ float g_agg [(size_t)NN_NODES * EMB];       // aggregated messages
__device__ float g_hmid[(size_t)NN_NODES * 2 * EMB];   // MLP hidden
__device__ float g_h2  [(size_t)NN_NODES * EMB];       // MLP out (pre-BN)

__device__ int   g_indeg[NN_NODES];
__device__ int   g_off  [NN_NODES];
__device__ int   g_ctr  [NN_NODES];
__device__ int   g_adj  [EE_EDGES];
__device__ int   g_cntb [NN_NODES * 4];
__device__ int   g_cntd [NN_NODES * 4];
__device__ float g_stats[2 * EMB];
__device__ float g_scale[EMB];
__device__ float g_shift[EMB];

// ----------------------------------------------------------------------------
__global__ void zero_scratch_kernel() {
    int t = blockIdx.x * blockDim.x + threadIdx.x;
    int stride = gridDim.x * blockDim.x;
    for (int i = t; i < NN_NODES; i += stride) { g_indeg[i] = 0; g_ctr[i] = 0; }
    for (int i = t; i < NN_NODES * 4; i += stride) { g_cntb[i] = 0; g_cntd[i] = 0; }
}

__global__ void zero_stats_kernel() {
    if (threadIdx.x < 2 * EMB) g_stats[threadIdx.x] = 0.0f;
}

// ----------------------------------------------------------------------------
__global__ void hist_kernel(const int* __restrict__ src, const int* __restrict__ dst,
                            const int* __restrict__ bond, const int* __restrict__ dir) {
    int e = blockIdx.x * blockDim.x + threadIdx.x;
    if (e >= EE_EDGES) return;
    int d = dst[e];
    atomicAdd(&g_indeg[d], 1);
    atomicAdd(&g_cntb[d * 4 + bond[e]], 1);
    atomicAdd(&g_cntd[d * 4 + dir[e]], 1);
}

// ----------------------------------------------------------------------------
__global__ void scan_kernel() {
    __shared__ int s[1024];
    __shared__ int carry;
    int t = threadIdx.x;
    if (t == 0) carry = 0;
    __syncthreads();
    for (int base = 0; base < NN_NODES; base += 1024) {
        int i = base + t;
        int v = (i < NN_NODES) ? g_indeg[i] : 0;
        s[t] = v;
        __syncthreads();
        #pragma unroll
        for (int off = 1; off < 1024; off <<= 1) {
            int x = (t >= off) ? s[t - off] : 0;
            __syncthreads();
            s[t] += x;
            __syncthreads();
        }
        int incl = s[t];
        int c = carry;
        if (i < NN_NODES) g_off[i] = c + incl - v;
        __syncthreads();
        if (t == 1023) carry = c + s[1023];
        __syncthreads();
    }
}

// ----------------------------------------------------------------------------
__global__ void fill_kernel(const int* __restrict__ src, const int* __restrict__ dst) {
    int e = blockIdx.x * blockDim.x + threadIdx.x;
    if (e >= EE_EDGES) return;
    int d = dst[e];
    int p = atomicAdd(&g_ctr[d], 1);
    g_adj[g_off[d] + p] = src[e];
}

// ----------------------------------------------------------------------------
__global__ void init_h_kernel(const int* __restrict__ x_atom, const int* __restrict__ x_chir,
                              const float* __restrict__ atom_emb, const float* __restrict__ chir_emb) {
    int t = blockIdx.x * blockDim.x + threadIdx.x;
    if (t >= NN_NODES * (EMB / 4)) return;
    int row = t >> 6;
    int q = t & 63;
    int a = x_atom[row];
    int c = x_chir[row];
    float4 va = reinterpret_cast<const float4*>(atom_emb)[a * 64 + q];
    float4 vc = reinterpret_cast<const float4*>(chir_emb)[c * 64 + q];
    float4 o;
    o.x = va.x + vc.x; o.y = va.y + vc.y; o.z = va.z + vc.z; o.w = va.w + vc.w;
    reinterpret_cast<float4*>(g_h)[t] = o;
}

// ----------------------------------------------------------------------------
// Aggregation: one warp per node (CSR gather, edge embeddings via counts).
// ----------------------------------------------------------------------------
__global__ void agg_kernel(const float* __restrict__ bondE,   // 6x256 (rows 0..4 used)
                           const float* __restrict__ dirE) {  // 3x256
    __shared__ float sBE[5 * EMB];
    __shared__ float sDE[3 * EMB];
    int tid = threadIdx.x;
    for (int i = tid; i < 5 * EMB; i += 256) sBE[i] = bondE[i];
    for (int i = tid; i < 3 * EMB; i += 256) sDE[i] = dirE[i];
    __syncthreads();

    int warp = tid >> 5, lane = tid & 31;
    int node = blockIdx.x * 8 + warp;
    if (node >= NN_NODES) return;
    int c0 = lane * 8;

    const float4* hrow = reinterpret_cast<const float4*>(g_h + (size_t)node * EMB + c0);
    float4 a0 = hrow[0], a1 = hrow[1];
    float acc[8] = {a0.x, a0.y, a0.z, a0.w, a1.x, a1.y, a1.z, a1.w};

    float fb0 = (float)g_cntb[node * 4 + 0];
    float fb1 = (float)g_cntb[node * 4 + 1];
    float fb2 = (float)g_cntb[node * 4 + 2];
    float fb3 = (float)g_cntb[node * 4 + 3];
    float fd0 = (float)g_cntd[node * 4 + 0] + 1.0f;   // + self loop dir 0
    float fd1 = (float)g_cntd[node * 4 + 1];
    float fd2 = (float)g_cntd[node * 4 + 2];

    #pragma unroll
    for (int c = 0; c < 8; c++) {
        int cc = c0 + c;
        float v = sBE[4 * EMB + cc];                  // self loop bond 4
        v += fb0 * sBE[0 * EMB + cc] + fb1 * sBE[1 * EMB + cc]
           + fb2 * sBE[2 * EMB + cc] + fb3 * sBE[3 * EMB + cc];
        v += fd0 * sDE[0 * EMB + cc] + fd1 * sDE[1 * EMB + cc] + fd2 * sDE[2 * EMB + cc];
        acc[c] += v;
    }

    int s = g_off[node];
    int deg = g_indeg[node];
    for (int e = s; e < s + deg; e++) {
        int j = __ldg(&g_adj[e]);
        const float4* hj = reinterpret_cast<const float4*>(g_h + (size_t)j * EMB + c0);
        float4 b0 = hj[0], b1 = hj[1];
        acc[0] += b0.x; acc[1] += b0.y; acc[2] += b0.z; acc[3] += b0.w;
        acc[4] += b1.x; acc[5] += b1.y; acc[6] += b1.z; acc[7] += b1.w;
    }

    float4 o0 = make_float4(acc[0], acc[1], acc[2], acc[3]);
    float4 o1 = make_float4(acc[4], acc[5], acc[6], acc[7]);
    float4* arow = reinterpret_cast<float4*>(g_agg + (size_t)node * EMB + c0);
    arow[0] = o0; arow[1] = o1;
}

// ----------------------------------------------------------------------------
// Split-BF16 tensor-core GEMM (3 passes on m16n8k16.bf16):
//   x = hi + lo, hi = bf16(x), lo = bf16(x - hi)  (effective ~16-bit mantissa)
//   D += Ahi*Bhi + Ahi*Blo + Alo*Bhi   (lo*lo dropped, ~2^-16 relative)
// Block tile 128x128, BK=32 elements, 256 threads = 8 warps (2x4, 64x32 warp).
//   SEL=0: A=g_agg  (K=256), C=g_hmid (NC=512)
//   SEL=1: A=g_hmid (K=512), C=g_h2   (NC=256), STATS -> g_stats
// ----------------------------------------------------------------------------
__device__ __forceinline__ void mma_bf16(float d[4], const uint32_t a[4], const uint32_t b[2]) {
    asm volatile(
        "mma.sync.aligned.m16n8k16.row.col.f32.bf16.bf16.f32 "
        "{%0,%1,%2,%3}, {%4,%5,%6,%7}, {%8,%9}, {%0,%1,%2,%3};"
        : "+f"(d[0]), "+f"(d[1]), "+f"(d[2]), "+f"(d[3])
        : "r"(a[0]), "r"(a[1]), "r"(a[2]), "r"(a[3]), "r"(b[0]), "r"(b[1]));
}

__device__ __forceinline__ uint32_t pack2bf(float a, float b) {
    __nv_bfloat162 t = __floats2bfloat162_rn(a, b);
    return *reinterpret_cast<uint32_t*>(&t);
}

// split a pair of floats into hi-pair and lo-pair (packed bf16x2)
__device__ __forceinline__ void split_pair(float a, float b, uint32_t& hi, uint32_t& lo) {
    __nv_bfloat16 ha = __float2bfloat16_rn(a);
    __nv_bfloat16 hb = __float2bfloat16_rn(b);
    __nv_bfloat162 h; h.x = ha; h.y = hb;
    hi = *reinterpret_cast<uint32_t*>(&h);
    lo = pack2bf(a - __bfloat162float(ha), b - __bfloat162float(hb));
}

template <bool RELU, bool STATS, int SEL>
__global__ void __launch_bounds__(256)
gemm_tc_kernel(const float* __restrict__ W, const float* __restrict__ bias) {
    constexpr int M = NN_NODES;
    constexpr int K = (SEL == 0) ? EMB : 2 * EMB;
    constexpr int NC = (SEL == 0) ? 2 * EMB : EMB;
    const float* __restrict__ A = (SEL == 0) ? g_agg : g_hmid;
    float* __restrict__ C = (SEL == 0) ? g_hmid : g_h2;

    constexpr int BM = 128, BN = 128;
    constexpr int BK = 32;               // elements per tile
    constexpr int LDU = BK / 2 + 4;      // u32 (bf16-pair) stride = 20
    __shared__ uint32_t AsH[BM][LDU];
    __shared__ uint32_t AsL[BM][LDU];
    __shared__ uint32_t BsH[BN][LDU];
    __shared__ uint32_t BsL[BN][LDU];
    __shared__ float sSum[BN];
    __shared__ float sSq[BN];

    int tid = threadIdx.x;
    int wid = tid >> 5, lane = tid & 31;
    int wm = wid & 1;        // 0..1 : 64-row slab
    int wn = wid >> 1;       // 0..3 : 32-col slab
    int rowBase = blockIdx.x * BM;
    int colBase = blockIdx.y * BN;

    if (STATS && tid < BN) { sSum[tid] = 0.f; sSq[tid] = 0.f; }

    float d[4][4][4];  // [mf][nf][reg]
    #pragma unroll
    for (int i = 0; i < 4; i++)
        #pragma unroll
        for (int j = 0; j < 4; j++)
            #pragma unroll
            for (int r = 0; r < 4; r++) d[i][j][r] = 0.0f;

    int gid = lane >> 2;   // 0..7
    int tig = lane & 3;    // 0..3

    for (int k0 = 0; k0 < K; k0 += BK) {
        // --- stage tiles: 128 rows x 8 float4 per matrix = 1024 slots, 4/thread ---
        #pragma unroll
        for (int r = 0; r < 4; r++) {
            int s = tid + 256 * r;
            int row = s >> 3;            // 0..127
            int fq = s & 7;              // float4 index within row
            // A
            int grow = rowBase + row;
            float4 va = (grow < M)
                ? *reinterpret_cast<const float4*>(A + (size_t)grow * K + k0 + fq * 4)
                : make_float4(0.f, 0.f, 0.f, 0.f);
            uint32_t h0, l0, h1, l1;
            split_pair(va.x, va.y, h0, l0);
            split_pair(va.z, va.w, h1, l1);
            AsH[row][fq * 2] = h0; AsH[row][fq * 2 + 1] = h1;
            AsL[row][fq * 2] = l0; AsL[row][fq * 2 + 1] = l1;
            // B (W row = output col; NC divisible by 128 so always valid)
            float4 vb = *reinterpret_cast<const float4*>(W + (size_t)(colBase + row) * K + k0 + fq * 4);
            split_pair(vb.x, vb.y, h0, l0);
            split_pair(vb.z, vb.w, h1, l1);
            BsH[row][fq * 2] = h0; BsH[row][fq * 2 + 1] = h1;
            BsL[row][fq * 2] = l0; BsL[row][fq * 2 + 1] = l1;
        }
        __syncthreads();

        // two K=16 steps per tile
        #pragma unroll
        for (int ks = 0; ks < 2; ks++) {
            int base = ks * 8;           // u32 (pair) offset
            uint32_t bh[4][2], bl[4][2];
            #pragma unroll
            for (int nf = 0; nf < 4; nf++) {
                int n = wn * 32 + nf * 8 + gid;
                bh[nf][0] = BsH[n][base + tig];
                bh[nf][1] = BsH[n][base + tig + 4];
                bl[nf][0] = BsL[n][base + tig];
                bl[nf][1] = BsL[n][base + tig + 4];
            }
            #pragma unroll
            for (int mf = 0; mf < 4; mf++) {
                int r0 = wm * 64 + mf * 16 + gid;
                uint32_t ah[4], al[4];
                ah[0] = AsH[r0][base + tig];
                ah[1] = AsH[r0 + 8][base + tig];
                ah[2] = AsH[r0][base + tig + 4];
                ah[3] = AsH[r0 + 8][base + tig + 4];
                al[0] = AsL[r0][base + tig];
                al[1] = AsL[r0 + 8][base + tig];
                al[2] = AsL[r0][base + tig + 4];
                al[3] = AsL[r0 + 8][base + tig + 4];
                #pragma unroll
                for (int nf = 0; nf < 4; nf++) {
                    mma_bf16(d[mf][nf], ah, bh[nf]);   // hi*hi
                    mma_bf16(d[mf][nf], ah, bl[nf]);   // hi*lo
                    mma_bf16(d[mf][nf], al, bh[nf]);   // lo*hi
                }
            }
        }
        __syncthreads();
    }

    // --- epilogue ---
    #pragma unroll
    for (int nf = 0; nf < 4; nf++) {
        int col = colBase + wn * 32 + nf * 8 + tig * 2;
        int lcol = wn * 32 + nf * 8 + tig * 2;
        float b0 = __ldg(&bias[col]);
        float b1 = __ldg(&bias[col + 1]);
        float s0 = 0.f, q0 = 0.f, s1 = 0.f, q1 = 0.f;
        #pragma unroll
        for (int mf = 0; mf < 4; mf++) {
            int row = rowBase + wm * 64 + mf * 16 + gid;
            if (row < M) {
                float v0 = d[mf][nf][0] + b0;
                float v1 = d[mf][nf][1] + b1;
                if (RELU) { v0 = fmaxf(v0, 0.f); v1 = fmaxf(v1, 0.f); }
                C[(size_t)row * NC + col] = v0;
                C[(size_t)row * NC + col + 1] = v1;
                if (STATS) { s0 += v0; q0 += v0 * v0; s1 += v1; q1 += v1 * v1; }
            }
            if (row + 8 < M) {
                float v2 = d[mf][nf][2] + b0;
                float v3 = d[mf][nf][3] + b1;
                if (RELU) { v2 = fmaxf(v2, 0.f); v3 = fmaxf(v3, 0.f); }
                C[(size_t)(row + 8) * NC + col] = v2;
                C[(size_t)(row + 8) * NC + col + 1] = v3;
                if (STATS) { s0 += v2; q0 += v2 * v2; s1 += v3; q1 += v3 * v3; }
            }
        }
        if (STATS) {
            atomicAdd(&sSum[lcol], s0); atomicAdd(&sSq[lcol], q0);
            atomicAdd(&sSum[lcol + 1], s1); atomicAdd(&sSq[lcol + 1], q1);
        }
    }
    if (STATS) {
        __syncthreads();
        if (tid < BN) {
            atomicAdd(&g_stats[colBase + tid], sSum[tid]);
            atomicAdd(&g_stats[EMB + colBase + tid], sSq[tid]);
        }
    }
}

// ----------------------------------------------------------------------------
__global__ void bn_finalize_kernel(const float* __restrict__ bn_w, const float* __restrict__ bn_b) {
    int c = threadIdx.x;
    if (c >= EMB) return;
    float invN = 1.0f / (float)NN_NODES;
    float mean = g_stats[c] * invN;
    float var = g_stats[EMB + c] * invN - mean * mean;
    float sc = bn_w[c] * rsqrtf(var + BN_EPS);
    g_scale[c] = sc;
    g_shift[c] = bn_b[c] - mean * sc;
}

// ----------------------------------------------------------------------------
__global__ void bn_apply_kernel(float* __restrict__ out_ext, int relu, int use_ext) {
    int t = blockIdx.x * blockDim.x + threadIdx.x;
    if (t >= NN_NODES * (EMB / 4)) return;
    int q = t & 63;
    float4 v = reinterpret_cast<const float4*>(g_h2)[t];
    float4 sc = reinterpret_cast<const float4*>(g_scale)[q];
    float4 sh = reinterpret_cast<const float4*>(g_shift)[q];
    v.x = v.x * sc.x + sh.x;
    v.y = v.y * sc.y + sh.y;
    v.z = v.z * sc.z + sh.z;
    v.w = v.w * sc.w + sh.w;
    if (relu) {
        v.x = fmaxf(v.x, 0.f); v.y = fmaxf(v.y, 0.f);
        v.z = fmaxf(v.z, 0.f); v.w = fmaxf(v.w, 0.f);
    }
    float4* dst = use_ext ? reinterpret_cast<float4*>(out_ext)
                          : reinterpret_cast<float4*>(g_h);
    dst[t] = v;
}

// ----------------------------------------------------------------------------
extern "C" void kernel_launch(void* const* d_in, const int* in_sizes, int n_in,
                              void* d_out, int out_size) {
    const int*   x_atom    = (const int*)d_in[0];
    const int*   x_chir    = (const int*)d_in[1];
    const int*   edge_idx  = (const int*)d_in[2];    // [2,E]
    const int*   edge_bond = (const int*)d_in[3];
    const int*   edge_dir  = (const int*)d_in[4];
    const float* atom_emb  = (const float*)d_in[5];  // [120,256]
    const float* chir_emb  = (const float*)d_in[6];  // [3,256]
    const float* bond_embs = (const float*)d_in[7];  // [5,6,256]
    const float* dir_embs  = (const float*)d_in[8];  // [5,3,256]
    const float* W1s       = (const float*)d_in[9];  // [5,512,256]
    const float* b1s       = (const float*)d_in[10]; // [5,512]
    const float* W2s       = (const float*)d_in[11]; // [5,256,512]
    const float* b2s       = (const float*)d_in[12]; // [5,256]
    const float* bn_w      = (const float*)d_in[13]; // [5,256]
    const float* bn_b      = (const float*)d_in[14]; // [5,256]
    float* out = (float*)d_out;

    const int* src = edge_idx;
    const int* dst = edge_idx + EE_EDGES;

    // --- preprocessing ---
    zero_scratch_kernel<<<512, 256>>>();
    hist_kernel<<<cdiv(EE_EDGES, 256), 256>>>(src, dst, edge_bond, edge_dir);
    scan_kernel<<<1, 1024>>>();
    fill_kernel<<<cdiv(EE_EDGES, 256), 256>>>(src, dst);
    init_h_kernel<<<cdiv(NN_NODES * (EMB / 4), 256), 256>>>(x_atom, x_chir, atom_emb, chir_emb);

    dim3 g1(cdiv(NN_NODES, 128), 2 * EMB / 128);  // 782 x 4
    dim3 g2(cdiv(NN_NODES, 128), EMB / 128);      // 782 x 2
    int aggBlocks = cdiv(NN_NODES, 8);
    int applyBlocks = cdiv(NN_NODES * (EMB / 4), 256);

    for (int l = 0; l < NUM_LAYER; l++) {
        const float* BE = bond_embs + (size_t)l * 6 * EMB;
        const float* DE = dir_embs + (size_t)l * 3 * EMB;
        const float* W1 = W1s + (size_t)l * 2 * EMB * EMB;
        const float* B1 = b1s + (size_t)l * 2 * EMB;
        const float* W2 = W2s + (size_t)l * EMB * 2 * EMB;
        const float* B2 = b2s + (size_t)l * EMB;

        agg_kernel<<<aggBlocks, 256>>>(BE, DE);
        gemm_tc_kernel<true, false, 0><<<g1, 256>>>(W1, B1);   // hmid = relu(agg@W1^T+b1)
        zero_stats_kernel<<<1, 512>>>();
        gemm_tc_kernel<false, true, 1><<<g2, 256>>>(W2, B2);   // h2 = hmid@W2^T+b2 (+stats)
        bn_finalize_kernel<<<1, 256>>>(bn_w + l * EMB, bn_b + l * EMB);

        int last = (l == NUM_LAYER - 1);
        bn_apply_kernel<<<applyBlocks, 256>>>(out, last ? 0 : 1, last ? 1 : 0);
    }
}

// round 7
// speedup vs baseline: 1.6927x; 1.6927x over previous
#include <cuda_runtime.h>
#include <cuda_bf16.h>
#include <cstdint>

#define NN_NODES 100000
#define EE_EDGES 300000
#define EMB 256
#define NUM_LAYER 5
#define BN_EPS 1e-5f

static inline int cdiv(int a, int b) { return (a + b - 1) / b; }

// ----------------------------------------------------------------------------
// Device scratch. Symbols only referenced from device code.
// Split-bf16 format: element pair (k, k+1) packed as bf16x2 in one u32;
// value = hi + lo with hi = bf16(x), lo = bf16(x - hi)  (~16-bit mantissa).
// ----------------------------------------------------------------------------
__device__ float    g_h   [(size_t)NN_NODES * EMB];          // node features (fp32)
__device__ float    g_h2  [(size_t)NN_NODES * EMB];          // MLP out pre-BN (fp32)
__device__ uint32_t g_aggH[(size_t)NN_NODES * (EMB / 2)];    // agg split (K=256 -> 128 pairs)
__device__ uint32_t g_aggL[(size_t)NN_NODES * (EMB / 2)];
__device__ uint32_t g_hmidH[(size_t)NN_NODES * EMB];         // hmid split (K=512 -> 256 pairs)
__device__ uint32_t g_hmidL[(size_t)NN_NODES * EMB];
__device__ uint32_t g_w1H[NUM_LAYER * 512 * 128];            // W1 split [5][512][128 pairs]
__device__ uint32_t g_w1L[NUM_LAYER * 512 * 128];
__device__ uint32_t g_w2H[NUM_LAYER * 256 * 256];            // W2 split [5][256][256 pairs]
__device__ uint32_t g_w2L[NUM_LAYER * 256 * 256];

__device__ int   g_indeg[NN_NODES];
__device__ int   g_off  [NN_NODES];
__device__ int   g_ctr  [NN_NODES];
__device__ int   g_adj  [EE_EDGES];
__device__ int   g_cntb [NN_NODES * 4];
__device__ int   g_cntd [NN_NODES * 4];
__device__ float g_stats[2 * EMB];
__device__ float g_scale[EMB];
__device__ float g_shift[EMB];

// ----------------------------------------------------------------------------
__device__ __forceinline__ uint32_t pack2bf(float a, float b) {
    __nv_bfloat162 t = __floats2bfloat162_rn(a, b);
    return *reinterpret_cast<uint32_t*>(&t);
}

__device__ __forceinline__ void split_pair(float a, float b, uint32_t& hi, uint32_t& lo) {
    __nv_bfloat16 ha = __float2bfloat16_rn(a);
    __nv_bfloat16 hb = __float2bfloat16_rn(b);
    __nv_bfloat162 h; h.x = ha; h.y = hb;
    hi = *reinterpret_cast<uint32_t*>(&h);
    lo = pack2bf(a - __bfloat162float(ha), b - __bfloat162float(hb));
}

// ----------------------------------------------------------------------------
__global__ void zero_scratch_kernel() {
    int t = blockIdx.x * blockDim.x + threadIdx.x;
    int stride = gridDim.x * blockDim.x;
    for (int i = t; i < NN_NODES; i += stride) { g_indeg[i] = 0; g_ctr[i] = 0; }
    for (int i = t; i < NN_NODES * 4; i += stride) { g_cntb[i] = 0; g_cntd[i] = 0; }
}

__global__ void zero_stats_kernel() {
    if (threadIdx.x < 2 * EMB) g_stats[threadIdx.x] = 0.0f;
}

// ----------------------------------------------------------------------------
// Pre-split all layer weights into bf16 hi/lo pair format (once per launch).
// W1s flat: 5*512*256 f32 = 327680 pairs; W2s flat: 5*256*512 = 327680 pairs.
// ----------------------------------------------------------------------------
__global__ void split_w_kernel(const float* __restrict__ W1s, const float* __restrict__ W2s) {
    constexpr int NP = NUM_LAYER * 512 * 128;   // pairs in each of W1/W2
    int t = blockIdx.x * blockDim.x + threadIdx.x;
    if (t < NP) {
        float a = W1s[2 * t], b = W1s[2 * t + 1];
        uint32_t hi, lo;
        split_pair(a, b, hi, lo);
        g_w1H[t] = hi; g_w1L[t] = lo;
    } else if (t < 2 * NP) {
        int u = t - NP;
        float a = W2s[2 * u], b = W2s[2 * u + 1];
        uint32_t hi, lo;
        split_pair(a, b, hi, lo);
        g_w2H[u] = hi; g_w2L[u] = lo;
    }
}

// ----------------------------------------------------------------------------
__global__ void hist_kernel(const int* __restrict__ src, const int* __restrict__ dst,
                            const int* __restrict__ bond, const int* __restrict__ dir) {
    int e = blockIdx.x * blockDim.x + threadIdx.x;
    if (e >= EE_EDGES) return;
    int d = dst[e];
    atomicAdd(&g_indeg[d], 1);
    atomicAdd(&g_cntb[d * 4 + bond[e]], 1);
    atomicAdd(&g_cntd[d * 4 + dir[e]], 1);
}

// ----------------------------------------------------------------------------
__global__ void scan_kernel() {
    __shared__ int s[1024];
    __shared__ int carry;
    int t = threadIdx.x;
    if (t == 0) carry = 0;
    __syncthreads();
    for (int base = 0; base < NN_NODES; base += 1024) {
        int i = base + t;
        int v = (i < NN_NODES) ? g_indeg[i] : 0;
        s[t] = v;
        __syncthreads();
        #pragma unroll
        for (int off = 1; off < 1024; off <<= 1) {
            int x = (t >= off) ? s[t - off] : 0;
            __syncthreads();
            s[t] += x;
            __syncthreads();
        }
        int incl = s[t];
        int c = carry;
        if (i < NN_NODES) g_off[i] = c + incl - v;
        __syncthreads();
        if (t == 1023) carry = c + s[1023];
        __syncthreads();
    }
}

// ----------------------------------------------------------------------------
__global__ void fill_kernel(const int* __restrict__ src, const int* __restrict__ dst) {
    int e = blockIdx.x * blockDim.x + threadIdx.x;
    if (e >= EE_EDGES) return;
    int d = dst[e];
    int p = atomicAdd(&g_ctr[d], 1);
    g_adj[g_off[d] + p] = src[e];
}

// ----------------------------------------------------------------------------
__global__ void init_h_kernel(const int* __restrict__ x_atom, const int* __restrict__ x_chir,
                              const float* __restrict__ atom_emb, const float* __restrict__ chir_emb) {
    int t = blockIdx.x * blockDim.x + threadIdx.x;
    if (t >= NN_NODES * (EMB / 4)) return;
    int row = t >> 6;
    int q = t & 63;
    int a = x_atom[row];
    int c = x_chir[row];
    float4 va = reinterpret_cast<const float4*>(atom_emb)[a * 64 + q];
    float4 vc = reinterpret_cast<const float4*>(chir_emb)[c * 64 + q];
    float4 o;
    o.x = va.x + vc.x; o.y = va.y + vc.y; o.z = va.z + vc.z; o.w = va.w + vc.w;
    reinterpret_cast<float4*>(g_h)[t] = o;
}

// ----------------------------------------------------------------------------
// Aggregation: one warp per node. fp32 accumulate, write split-bf16 output
// (directly consumable by GEMM1's A staging).
// ----------------------------------------------------------------------------
__global__ void agg_kernel(const float* __restrict__ bondE,   // 6x256 (rows 0..4 used)
                           const float* __restrict__ dirE) {  // 3x256
    __shared__ float sBE[5 * EMB];
    __shared__ float sDE[3 * EMB];
    int tid = threadIdx.x;
    for (int i = tid; i < 5 * EMB; i += 256) sBE[i] = bondE[i];
    for (int i = tid; i < 3 * EMB; i += 256) sDE[i] = dirE[i];
    __syncthreads();

    int warp = tid >> 5, lane = tid & 31;
    int node = blockIdx.x * 8 + warp;
    if (node >= NN_NODES) return;
    int c0 = lane * 8;

    const float4* hrow = reinterpret_cast<const float4*>(g_h + (size_t)node * EMB + c0);
    float4 a0 = hrow[0], a1 = hrow[1];
    float acc[8] = {a0.x, a0.y, a0.z, a0.w, a1.x, a1.y, a1.z, a1.w};

    float fb0 = (float)g_cntb[node * 4 + 0];
    float fb1 = (float)g_cntb[node * 4 + 1];
    float fb2 = (float)g_cntb[node * 4 + 2];
    float fb3 = (float)g_cntb[node * 4 + 3];
    float fd0 = (float)g_cntd[node * 4 + 0] + 1.0f;   // + self loop dir 0
    float fd1 = (float)g_cntd[node * 4 + 1];
    float fd2 = (float)g_cntd[node * 4 + 2];

    #pragma unroll
    for (int c = 0; c < 8; c++) {
        int cc = c0 + c;
        float v = sBE[4 * EMB + cc];                  // self loop bond 4
        v += fb0 * sBE[0 * EMB + cc] + fb1 * sBE[1 * EMB + cc]
           + fb2 * sBE[2 * EMB + cc] + fb3 * sBE[3 * EMB + cc];
        v += fd0 * sDE[0 * EMB + cc] + fd1 * sDE[1 * EMB + cc] + fd2 * sDE[2 * EMB + cc];
        acc[c] += v;
    }

    int s = g_off[node];
    int deg = g_indeg[node];
    for (int e = s; e < s + deg; e++) {
        int j = __ldg(&g_adj[e]);
        const float4* hj = reinterpret_cast<const float4*>(g_h + (size_t)j * EMB + c0);
        float4 b0 = hj[0], b1 = hj[1];
        acc[0] += b0.x; acc[1] += b0.y; acc[2] += b0.z; acc[3] += b0.w;
        acc[4] += b1.x; acc[5] += b1.y; acc[6] += b1.z; acc[7] += b1.w;
    }

    // split to bf16 hi/lo pairs (4 pairs per lane, 16B aligned)
    uint4 hv, lv;
    split_pair(acc[0], acc[1], hv.x, lv.x);
    split_pair(acc[2], acc[3], hv.y, lv.y);
    split_pair(acc[4], acc[5], hv.z, lv.z);
    split_pair(acc[6], acc[7], hv.w, lv.w);
    size_t base = (size_t)node * (EMB / 2) + lane * 4;
    *reinterpret_cast<uint4*>(&g_aggH[base]) = hv;
    *reinterpret_cast<uint4*>(&g_aggL[base]) = lv;
}

// ----------------------------------------------------------------------------
// Split-BF16 tensor-core GEMM (3 passes of m16n8k16.bf16):
//   D += Ahi*Bhi + Ahi*Blo + Alo*Bhi
// A and W are PRE-SPLIT in global memory -> staging is pure LDG.128/STS.128.
// Block tile 128x128, BK=32 elements (16 pairs), 256 thr = 8 warps (2x4).
//   SEL=0: A=g_agg[H|L] (K=256), out = g_hmid[H|L] split + ReLU (NC=512)
//   SEL=1: A=g_hmid[H|L] (K=512), out = g_h2 fp32 + BN stats (NC=256)
// ----------------------------------------------------------------------------
__device__ __forceinline__ void mma_bf16(float d[4], const uint32_t a[4], const uint32_t b[2]) {
    asm volatile(
        "mma.sync.aligned.m16n8k16.row.col.f32.bf16.bf16.f32 "
        "{%0,%1,%2,%3}, {%4,%5,%6,%7}, {%8,%9}, {%0,%1,%2,%3};"
        : "+f"(d[0]), "+f"(d[1]), "+f"(d[2]), "+f"(d[3])
        : "r"(a[0]), "r"(a[1]), "r"(a[2]), "r"(a[3]), "r"(b[0]), "r"(b[1]));
}

template <int SEL>
__global__ void __launch_bounds__(256)
gemm_tc_kernel(const float* __restrict__ bias, int layer) {
    constexpr int M = NN_NODES;
    constexpr int K = (SEL == 0) ? EMB : 2 * EMB;
    constexpr int NC = (SEL == 0) ? 2 * EMB : EMB;
    constexpr int KP = K / 2;                         // pairs per A row
    const uint32_t* __restrict__ AH = (SEL == 0) ? g_aggH : g_hmidH;
    const uint32_t* __restrict__ AL = (SEL == 0) ? g_aggL : g_hmidL;
    const uint32_t* __restrict__ WH = ((SEL == 0) ? g_w1H : g_w2H) + (size_t)layer * NC * KP;
    const uint32_t* __restrict__ WL = ((SEL == 0) ? g_w1L : g_w2L) + (size_t)layer * NC * KP;

    constexpr int BM = 128, BN = 128;
    constexpr int BKP = 16;              // pairs per K-tile (32 elements)
    constexpr int LDU = BKP + 4;         // u32 stride 20 -> conflict-free frags
    __shared__ uint32_t AsH[BM][LDU];
    __shared__ uint32_t AsL[BM][LDU];
    __shared__ uint32_t BsH[BN][LDU];
    __shared__ uint32_t BsL[BN][LDU];
    __shared__ float sSum[BN];
    __shared__ float sSq[BN];

    int tid = threadIdx.x;
    int wid = tid >> 5, lane = tid & 31;
    int wm = wid & 1;        // 0..1 : 64-row slab
    int wn = wid >> 1;       // 0..3 : 32-col slab
    int rowBase = blockIdx.x * BM;
    int colBase = blockIdx.y * BN;

    if (SEL == 1 && tid < BN) { sSum[tid] = 0.f; sSq[tid] = 0.f; }

    float d[4][4][4];  // [mf][nf][reg]
    #pragma unroll
    for (int i = 0; i < 4; i++)
        #pragma unroll
        for (int j = 0; j < 4; j++)
            #pragma unroll
            for (int r = 0; r < 4; r++) d[i][j][r] = 0.0f;

    int gid = lane >> 2;   // 0..7
    int tig = lane & 3;    // 0..3

    for (int kp0 = 0; kp0 < KP; kp0 += BKP) {
        // --- stage: 128 rows x 4 uint4 per array = 512 slots, 2 per thread ---
        #pragma unroll
        for (int r = 0; r < 2; r++) {
            int s = tid + 256 * r;
            int row = s >> 2;            // 0..127
            int fq = s & 3;              // uint4 index (4 pairs each)
            // A
            int grow = rowBase + row;
            uint4 vh = make_uint4(0, 0, 0, 0), vl = make_uint4(0, 0, 0, 0);
            if (grow < M) {
                size_t ab = (size_t)grow * KP + kp0 + fq * 4;
                vh = *reinterpret_cast<const uint4*>(AH + ab);
                vl = *reinterpret_cast<const uint4*>(AL + ab);
            }
            *reinterpret_cast<uint4*>(&AsH[row][fq * 4]) = vh;
            *reinterpret_cast<uint4*>(&AsL[row][fq * 4]) = vl;
            // B (W row = output col; NC divisible by 128 so always valid)
            size_t bb = (size_t)(colBase + row) * KP + kp0 + fq * 4;
            *reinterpret_cast<uint4*>(&BsH[row][fq * 4]) =
                *reinterpret_cast<const uint4*>(WH + bb);
            *reinterpret_cast<uint4*>(&BsL[row][fq * 4]) =
                *reinterpret_cast<const uint4*>(WL + bb);
        }
        __syncthreads();

        // two K=16 steps per tile
        #pragma unroll
        for (int ks = 0; ks < 2; ks++) {
            int base = ks * 8;           // pair offset
            uint32_t bh[4][2], bl[4][2];
            #pragma unroll
            for (int nf = 0; nf < 4; nf++) {
                int n = wn * 32 + nf * 8 + gid;
                bh[nf][0] = BsH[n][base + tig];
                bh[nf][1] = BsH[n][base + tig + 4];
                bl[nf][0] = BsL[n][base + tig];
                bl[nf][1] = BsL[n][base + tig + 4];
            }
            #pragma unroll
            for (int mf = 0; mf < 4; mf++) {
                int r0 = wm * 64 + mf * 16 + gid;
                uint32_t ah[4], al[4];
                ah[0] = AsH[r0][base + tig];
                ah[1] = AsH[r0 + 8][base + tig];
                ah[2] = AsH[r0][base + tig + 4];
                ah[3] = AsH[r0 + 8][base + tig + 4];
                al[0] = AsL[r0][base + tig];
                al[1] = AsL[r0 + 8][base + tig];
                al[2] = AsL[r0][base + tig + 4];
                al[3] = AsL[r0 + 8][base + tig + 4];
                #pragma unroll
                for (int nf = 0; nf < 4; nf++) {
                    mma_bf16(d[mf][nf], ah, bh[nf]);   // hi*hi
                    mma_bf16(d[mf][nf], ah, bl[nf]);   // hi*lo
                    mma_bf16(d[mf][nf], al, bh[nf]);   // lo*hi
                }
            }
        }
        __syncthreads();
    }

    // --- epilogue ---
    #pragma unroll
    for (int nf = 0; nf < 4; nf++) {
        int col = colBase + wn * 32 + nf * 8 + tig * 2;   // even
        int lcol = wn * 32 + nf * 8 + tig * 2;
        float b0 = __ldg(&bias[col]);
        float b1 = __ldg(&bias[col + 1]);
        float s0 = 0.f, q0 = 0.f, s1 = 0.f, q1 = 0.f;
        #pragma unroll
        for (int mf = 0; mf < 4; mf++) {
            int row = rowBase + wm * 64 + mf * 16 + gid;
            if (row < M) {
                float v0 = d[mf][nf][0] + b0;
                float v1 = d[mf][nf][1] + b1;
                if (SEL == 0) {
                    v0 = fmaxf(v0, 0.f); v1 = fmaxf(v1, 0.f);
                    uint32_t hi, lo;
                    split_pair(v0, v1, hi, lo);
                    size_t p = (size_t)row * (NC / 2) + (col >> 1);
                    g_hmidH[p] = hi; g_hmidL[p] = lo;
                } else {
                    g_h2[(size_t)row * NC + col] = v0;
                    g_h2[(size_t)row * NC + col + 1] = v1;
                    s0 += v0; q0 += v0 * v0; s1 += v1; q1 += v1 * v1;
                }
            }
            if (row + 8 < M) {
                float v2 = d[mf][nf][2] + b0;
                float v3 = d[mf][nf][3] + b1;
                if (SEL == 0) {
                    v2 = fmaxf(v2, 0.f); v3 = fmaxf(v3, 0.f);
                    uint32_t hi, lo;
                    split_pair(v2, v3, hi, lo);
                    size_t p = (size_t)(row + 8) * (NC / 2) + (col >> 1);
                    g_hmidH[p] = hi; g_hmidL[p] = lo;
                } else {
                    g_h2[(size_t)(row + 8) * NC + col] = v2;
                    g_h2[(size_t)(row + 8) * NC + col + 1] = v3;
                    s0 += v2; q0 += v2 * v2; s1 += v3; q1 += v3 * v3;
                }
            }
        }
        if (SEL == 1) {
            atomicAdd(&sSum[lcol], s0); atomicAdd(&sSq[lcol], q0);
            atomicAdd(&sSum[lcol + 1], s1); atomicAdd(&sSq[lcol + 1], q1);
        }
    }
    if (SEL == 1) {
        __syncthreads();
        if (tid < BN) {
            atomicAdd(&g_stats[colBase + tid], sSum[tid]);
            atomicAdd(&g_stats[EMB + colBase + tid], sSq[tid]);
        }
    }
}

// ----------------------------------------------------------------------------
__global__ void bn_finalize_kernel(const float* __restrict__ bn_w, const float* __restrict__ bn_b) {
    int c = threadIdx.x;
    if (c >= EMB) return;
    float invN = 1.0f / (float)NN_NODES;
    float mean = g_stats[c] * invN;
    float var = g_stats[EMB + c] * invN - mean * mean;
    float sc = bn_w[c] * rsqrtf(var + BN_EPS);
    g_scale[c] = sc;
    g_shift[c] = bn_b[c] - mean * sc;
}

// ----------------------------------------------------------------------------
__global__ void bn_apply_kernel(float* __restrict__ out_ext, int relu, int use_ext) {
    int t = blockIdx.x * blockDim.x + threadIdx.x;
    if (t >= NN_NODES * (EMB / 4)) return;
    int q = t & 63;
    float4 v = reinterpret_cast<const float4*>(g_h2)[t];
    float4 sc = reinterpret_cast<const float4*>(g_scale)[q];
    float4 sh = reinterpret_cast<const float4*>(g_shift)[q];
    v.x = v.x * sc.x + sh.x;
    v.y = v.y * sc.y + sh.y;
    v.z = v.z * sc.z + sh.z;
    v.w = v.w * sc.w + sh.w;
    if (relu) {
        v.x = fmaxf(v.x, 0.f); v.y = fmaxf(v.y, 0.f);
        v.z = fmaxf(v.z, 0.f); v.w = fmaxf(v.w, 0.f);
    }
    float4* dst = use_ext ? reinterpret_cast<float4*>(out_ext)
                          : reinterpret_cast<float4*>(g_h);
    dst[t] = v;
}

// ----------------------------------------------------------------------------
extern "C" void kernel_launch(void* const* d_in, const int* in_sizes, int n_in,
                              void* d_out, int out_size) {
    const int*   x_atom    = (const int*)d_in[0];
    const int*   x_chir    = (const int*)d_in[1];
    const int*   edge_idx  = (const int*)d_in[2];    // [2,E]
    const int*   edge_bond = (const int*)d_in[3];
    const int*   edge_dir  = (const int*)d_in[4];
    const float* atom_emb  = (const float*)d_in[5];  // [120,256]
    const float* chir_emb  = (const float*)d_in[6];  // [3,256]
    const float* bond_embs = (const float*)d_in[7];  // [5,6,256]
    const float* dir_embs  = (const float*)d_in[8];  // [5,3,256]
    const float* W1s       = (const float*)d_in[9];  // [5,512,256]
    const float* b1s       = (const float*)d_in[10]; // [5,512]
    const float* W2s       = (const float*)d_in[11]; // [5,256,512]
    const float* b2s       = (const float*)d_in[12]; // [5,256]
    const float* bn_w      = (const float*)d_in[13]; // [5,256]
    const float* bn_b      = (const float*)d_in[14]; // [5,256]
    float* out = (float*)d_out;

    const int* src = edge_idx;
    const int* dst = edge_idx + EE_EDGES;

    // --- preprocessing ---
    zero_scratch_kernel<<<512, 256>>>();
    hist_kernel<<<cdiv(EE_EDGES, 256), 256>>>(src, dst, edge_bond, edge_dir);
    scan_kernel<<<1, 1024>>>();
    fill_kernel<<<cdiv(EE_EDGES, 256), 256>>>(src, dst);
    init_h_kernel<<<cdiv(NN_NODES * (EMB / 4), 256), 256>>>(x_atom, x_chir, atom_emb, chir_emb);
    split_w_kernel<<<cdiv(2 * NUM_LAYER * 512 * 128, 256), 256>>>(W1s, W2s);

    dim3 g1(cdiv(NN_NODES, 128), 2 * EMB / 128);  // 782 x 4
    dim3 g2(cdiv(NN_NODES, 128), EMB / 128);      // 782 x 2
    int aggBlocks = cdiv(NN_NODES, 8);
    int applyBlocks = cdiv(NN_NODES * (EMB / 4), 256);

    for (int l = 0; l < NUM_LAYER; l++) {
        const float* BE = bond_embs + (size_t)l * 6 * EMB;
        const float* DE = dir_embs + (size_t)l * 3 * EMB;
        const float* B1 = b1s + (size_t)l * 2 * EMB;
        const float* B2 = b2s + (size_t)l * EMB;

        agg_kernel<<<aggBlocks, 256>>>(BE, DE);
        gemm_tc_kernel<0><<<g1, 256>>>(B1, l);      // hmid = relu(agg@W1^T+b1), split out
        zero_stats_kernel<<<1, 512>>>();
        gemm_tc_kernel<1><<<g2, 256>>>(B2, l);      // h2 = hmid@W2^T+b2 (+stats)
        bn_finalize_kernel<<<1, 256>>>(bn_w + l * EMB, bn_b + l * EMB);

        int last = (l == NUM_LAYER - 1);
        bn_apply_kernel<<<applyBlocks, 256>>>(out, last ? 0 : 1, last ? 1 : 0);
    }
}

// round 8
// speedup vs baseline: 2.0831x; 1.2306x over previous
#include <cuda_runtime.h>
#include <cuda_bf16.h>
#include <cstdint>

#define NN_NODES 100000
#define EE_EDGES 300000
#define EMB 256
#define NUM_LAYER 5
#define BN_EPS 1e-5f

static inline int cdiv(int a, int b) { return (a + b - 1) / b; }

// ----------------------------------------------------------------------------
// Device scratch. Symbols only referenced from device code.
// Split-bf16: pair (k,k+1) packed bf16x2 in u32; value = hi + lo.
// ----------------------------------------------------------------------------
__device__ float    g_h   [(size_t)NN_NODES * EMB];          // layer-0 node features
__device__ float    g_h2  [(size_t)NN_NODES * EMB];          // MLP out pre-BN (fp32)
__device__ uint32_t g_aggH[(size_t)NN_NODES * (EMB / 2)];
__device__ uint32_t g_aggL[(size_t)NN_NODES * (EMB / 2)];
__device__ uint32_t g_hmidH[(size_t)NN_NODES * EMB];
__device__ uint32_t g_hmidL[(size_t)NN_NODES * EMB];
__device__ uint32_t g_w1H[NUM_LAYER * 512 * 128];
__device__ uint32_t g_w1L[NUM_LAYER * 512 * 128];
__device__ uint32_t g_w2H[NUM_LAYER * 256 * 256];
__device__ uint32_t g_w2L[NUM_LAYER * 256 * 256];

__device__ int   g_indeg[NN_NODES];
__device__ int   g_off  [NN_NODES];
__device__ int   g_ctr  [NN_NODES];
__device__ int   g_adj  [EE_EDGES];
__device__ int   g_cntb [NN_NODES * 4];
__device__ int   g_cntd [NN_NODES * 4];
__device__ float g_stats[2 * EMB];
__device__ float g_scale[EMB];
__device__ float g_shift[EMB];

// ----------------------------------------------------------------------------
__device__ __forceinline__ uint32_t pack2bf(float a, float b) {
    __nv_bfloat162 t = __floats2bfloat162_rn(a, b);
    return *reinterpret_cast<uint32_t*>(&t);
}

__device__ __forceinline__ void split_pair(float a, float b, uint32_t& hi, uint32_t& lo) {
    __nv_bfloat16 ha = __float2bfloat16_rn(a);
    __nv_bfloat16 hb = __float2bfloat16_rn(b);
    __nv_bfloat162 h; h.x = ha; h.y = hb;
    hi = *reinterpret_cast<uint32_t*>(&h);
    lo = pack2bf(a - __bfloat162float(ha), b - __bfloat162float(hb));
}

// ----------------------------------------------------------------------------
__global__ void zero_scratch_kernel() {
    int t = blockIdx.x * blockDim.x + threadIdx.x;
    int stride = gridDim.x * blockDim.x;
    for (int i = t; i < NN_NODES; i += stride) { g_indeg[i] = 0; g_ctr[i] = 0; }
    for (int i = t; i < NN_NODES * 4; i += stride) { g_cntb[i] = 0; g_cntd[i] = 0; }
}

__global__ void zero_stats_kernel() {
    if (threadIdx.x < 2 * EMB) g_stats[threadIdx.x] = 0.0f;
}

// ----------------------------------------------------------------------------
__global__ void split_w_kernel(const float* __restrict__ W1s, const float* __restrict__ W2s) {
    constexpr int NP = NUM_LAYER * 512 * 128;
    int t = blockIdx.x * blockDim.x + threadIdx.x;
    if (t < NP) {
        uint32_t hi, lo;
        split_pair(W1s[2 * t], W1s[2 * t + 1], hi, lo);
        g_w1H[t] = hi; g_w1L[t] = lo;
    } else if (t < 2 * NP) {
        int u = t - NP;
        uint32_t hi, lo;
        split_pair(W2s[2 * u], W2s[2 * u + 1], hi, lo);
        g_w2H[u] = hi; g_w2L[u] = lo;
    }
}

// ----------------------------------------------------------------------------
__global__ void hist_kernel(const int* __restrict__ src, const int* __restrict__ dst,
                            const int* __restrict__ bond, const int* __restrict__ dir) {
    int e = blockIdx.x * blockDim.x + threadIdx.x;
    if (e >= EE_EDGES) return;
    int d = dst[e];
    atomicAdd(&g_indeg[d], 1);
    atomicAdd(&g_cntb[d * 4 + bond[e]], 1);
    atomicAdd(&g_cntd[d * 4 + dir[e]], 1);
}

// ----------------------------------------------------------------------------
__global__ void scan_kernel() {
    __shared__ int s[1024];
    __shared__ int carry;
    int t = threadIdx.x;
    if (t == 0) carry = 0;
    __syncthreads();
    for (int base = 0; base < NN_NODES; base += 1024) {
        int i = base + t;
        int v = (i < NN_NODES) ? g_indeg[i] : 0;
        s[t] = v;
        __syncthreads();
        #pragma unroll
        for (int off = 1; off < 1024; off <<= 1) {
            int x = (t >= off) ? s[t - off] : 0;
            __syncthreads();
            s[t] += x;
            __syncthreads();
        }
        int incl = s[t];
        int c = carry;
        if (i < NN_NODES) g_off[i] = c + incl - v;
        __syncthreads();
        if (t == 1023) carry = c + s[1023];
        __syncthreads();
    }
}

// ----------------------------------------------------------------------------
__global__ void fill_kernel(const int* __restrict__ src, const int* __restrict__ dst) {
    int e = blockIdx.x * blockDim.x + threadIdx.x;
    if (e >= EE_EDGES) return;
    int d = dst[e];
    int p = atomicAdd(&g_ctr[d], 1);
    g_adj[g_off[d] + p] = src[e];
}

// ----------------------------------------------------------------------------
__global__ void init_h_kernel(const int* __restrict__ x_atom, const int* __restrict__ x_chir,
                              const float* __restrict__ atom_emb, const float* __restrict__ chir_emb) {
    int t = blockIdx.x * blockDim.x + threadIdx.x;
    if (t >= NN_NODES * (EMB / 4)) return;
    int row = t >> 6;
    int q = t & 63;
    int a = x_atom[row];
    int c = x_chir[row];
    float4 va = reinterpret_cast<const float4*>(atom_emb)[a * 64 + q];
    float4 vc = reinterpret_cast<const float4*>(chir_emb)[c * 64 + q];
    float4 o;
    o.x = va.x + vc.x; o.y = va.y + vc.y; o.z = va.z + vc.z; o.w = va.w + vc.w;
    reinterpret_cast<float4*>(g_h)[t] = o;
}

// ----------------------------------------------------------------------------
// Aggregation (one warp/node) with BN+ReLU fused on the INPUT side:
//   mode 0: rows come from g_h (layer 0 features, raw)
//   mode 1: rows come from g_h2 with v = relu(v*scale[c]+shift[c]) applied
// Writes split-bf16 output for GEMM1.
// ----------------------------------------------------------------------------
__global__ void agg_kernel(const float* __restrict__ bondE,   // 6x256 (rows 0..4 used)
                           const float* __restrict__ dirE,    // 3x256
                           int mode) {
    __shared__ float sBE[5 * EMB];
    __shared__ float sDE[3 * EMB];
    int tid = threadIdx.x;
    for (int i = tid; i < 5 * EMB; i += 256) sBE[i] = bondE[i];
    for (int i = tid; i < 3 * EMB; i += 256) sDE[i] = dirE[i];
    __syncthreads();

    int warp = tid >> 5, lane = tid & 31;
    int node = blockIdx.x * 8 + warp;
    if (node >= NN_NODES) return;
    int c0 = lane * 8;

    // per-lane BN transform for the 8 owned columns
    float sc[8], sh[8];
    {
        float4 s0 = *reinterpret_cast<const float4*>(g_scale + c0);
        float4 s1 = *reinterpret_cast<const float4*>(g_scale + c0 + 4);
        float4 h0 = *reinterpret_cast<const float4*>(g_shift + c0);
        float4 h1 = *reinterpret_cast<const float4*>(g_shift + c0 + 4);
        sc[0] = s0.x; sc[1] = s0.y; sc[2] = s0.z; sc[3] = s0.w;
        sc[4] = s1.x; sc[5] = s1.y; sc[6] = s1.z; sc[7] = s1.w;
        sh[0] = h0.x; sh[1] = h0.y; sh[2] = h0.z; sh[3] = h0.w;
        sh[4] = h1.x; sh[5] = h1.y; sh[6] = h1.z; sh[7] = h1.w;
    }

    const float* __restrict__ H = (mode == 0) ? g_h : g_h2;

    float acc[8];
    {   // self row
        const float4* hrow = reinterpret_cast<const float4*>(H + (size_t)node * EMB + c0);
        float4 a0 = hrow[0], a1 = hrow[1];
        float raw[8] = {a0.x, a0.y, a0.z, a0.w, a1.x, a1.y, a1.z, a1.w};
        #pragma unroll
        for (int c = 0; c < 8; c++)
            acc[c] = (mode == 0) ? raw[c] : fmaxf(fmaf(raw[c], sc[c], sh[c]), 0.f);
    }

    float fb0 = (float)g_cntb[node * 4 + 0];
    float fb1 = (float)g_cntb[node * 4 + 1];
    float fb2 = (float)g_cntb[node * 4 + 2];
    float fb3 = (float)g_cntb[node * 4 + 3];
    float fd0 = (float)g_cntd[node * 4 + 0] + 1.0f;   // + self loop dir 0
    float fd1 = (float)g_cntd[node * 4 + 1];
    float fd2 = (float)g_cntd[node * 4 + 2];

    #pragma unroll
    for (int c = 0; c < 8; c++) {
        int cc = c0 + c;
        float v = sBE[4 * EMB + cc];                  // self loop bond 4
        v += fb0 * sBE[0 * EMB + cc] + fb1 * sBE[1 * EMB + cc]
           + fb2 * sBE[2 * EMB + cc] + fb3 * sBE[3 * EMB + cc];
        v += fd0 * sDE[0 * EMB + cc] + fd1 * sDE[1 * EMB + cc] + fd2 * sDE[2 * EMB + cc];
        acc[c] += v;
    }

    int s = g_off[node];
    int deg = g_indeg[node];
    for (int e = s; e < s + deg; e++) {
        int j = __ldg(&g_adj[e]);
        const float4* hj = reinterpret_cast<const float4*>(H + (size_t)j * EMB + c0);
        float4 b0 = hj[0], b1 = hj[1];
        float raw[8] = {b0.x, b0.y, b0.z, b0.w, b1.x, b1.y, b1.z, b1.w};
        if (mode == 0) {
            #pragma unroll
            for (int c = 0; c < 8; c++) acc[c] += raw[c];
        } else {
            #pragma unroll
            for (int c = 0; c < 8; c++)
                acc[c] += fmaxf(fmaf(raw[c], sc[c], sh[c]), 0.f);
        }
    }

    uint4 hv, lv;
    split_pair(acc[0], acc[1], hv.x, lv.x);
    split_pair(acc[2], acc[3], hv.y, lv.y);
    split_pair(acc[4], acc[5], hv.z, lv.z);
    split_pair(acc[6], acc[7], hv.w, lv.w);
    size_t base = (size_t)node * (EMB / 2) + lane * 4;
    *reinterpret_cast<uint4*>(&g_aggH[base]) = hv;
    *reinterpret_cast<uint4*>(&g_aggL[base]) = lv;
}

// ----------------------------------------------------------------------------
// Split-BF16 tensor-core GEMM with ldmatrix fragment loads.
//   D += Ahi*Bhi + Ahi*Blo + Alo*Bhi   (m16n8k16.bf16)
// Block 128x128, BK=32 elements (16 pairs), 8 warps (2x4).
//   SEL=0: A=g_agg (K=256) -> g_hmid split + ReLU (NC=512)
//   SEL=1: A=g_hmid (K=512) -> g_h2 fp32 + BN stats (NC=256)
// ----------------------------------------------------------------------------
__device__ __forceinline__ void mma_bf16(float d[4], const uint32_t a[4], const uint32_t b[2]) {
    asm volatile(
        "mma.sync.aligned.m16n8k16.row.col.f32.bf16.bf16.f32 "
        "{%0,%1,%2,%3}, {%4,%5,%6,%7}, {%8,%9}, {%0,%1,%2,%3};"
        : "+f"(d[0]), "+f"(d[1]), "+f"(d[2]), "+f"(d[3])
        : "r"(a[0]), "r"(a[1]), "r"(a[2]), "r"(a[3]), "r"(b[0]), "r"(b[1]));
}

__device__ __forceinline__ void ldmx4(uint32_t* r, uint32_t addr) {
    asm volatile("ldmatrix.sync.aligned.m8n8.x4.shared.b16 {%0,%1,%2,%3}, [%4];"
                 : "=r"(r[0]), "=r"(r[1]), "=r"(r[2]), "=r"(r[3]) : "r"(addr));
}

template <int SEL>
__global__ void __launch_bounds__(256)
gemm_tc_kernel(const float* __restrict__ bias, int layer) {
    constexpr int M = NN_NODES;
    constexpr int K = (SEL == 0) ? EMB : 2 * EMB;
    constexpr int NC = (SEL == 0) ? 2 * EMB : EMB;
    constexpr int KP = K / 2;
    const uint32_t* __restrict__ AH = (SEL == 0) ? g_aggH : g_hmidH;
    const uint32_t* __restrict__ AL = (SEL == 0) ? g_aggL : g_hmidL;
    const uint32_t* __restrict__ WH = ((SEL == 0) ? g_w1H : g_w2H) + (size_t)layer * NC * KP;
    const uint32_t* __restrict__ WL = ((SEL == 0) ? g_w1L : g_w2L) + (size_t)layer * NC * KP;

    constexpr int BM = 128, BN = 128;
    constexpr int BKP = 16;              // pairs per K-tile
    constexpr int LDU = BKP + 4;         // stride 20 u32: ldmatrix conflict-free
    __shared__ uint32_t AsH[BM][LDU];
    __shared__ uint32_t AsL[BM][LDU];
    __shared__ uint32_t BsH[BN][LDU];
    __shared__ uint32_t BsL[BN][LDU];
    __shared__ float sSum[BN];
    __shared__ float sSq[BN];

    int tid = threadIdx.x;
    int wid = tid >> 5, lane = tid & 31;
    int wm = wid & 1;
    int wn = wid >> 1;
    int rowBase = blockIdx.x * BM;
    int colBase = blockIdx.y * BN;

    if (SEL == 1 && tid < BN) { sSum[tid] = 0.f; sSq[tid] = 0.f; }

    float d[4][4][4];
    #pragma unroll
    for (int i = 0; i < 4; i++)
        #pragma unroll
        for (int j = 0; j < 4; j++)
            #pragma unroll
            for (int r = 0; r < 4; r++) d[i][j][r] = 0.0f;

    int gid = lane >> 2;
    int tig = lane & 3;

    uint32_t aH_b = (uint32_t)__cvta_generic_to_shared(&AsH[0][0]);
    uint32_t aL_b = (uint32_t)__cvta_generic_to_shared(&AsL[0][0]);
    uint32_t bH_b = (uint32_t)__cvta_generic_to_shared(&BsH[0][0]);
    uint32_t bL_b = (uint32_t)__cvta_generic_to_shared(&BsL[0][0]);

    // ldmatrix lane-address components
    int aRow = wm * 64 + (lane & 15);          // + mf*16
    int aCol = (lane >> 4) * 4;                // + ks*8
    int bRow = wn * 32 + (lane & 7) + ((lane >> 4) << 3);  // + nfp*16
    int bCol = ((lane >> 3) & 1) * 4;          // + ks*8

    for (int kp0 = 0; kp0 < KP; kp0 += BKP) {
        #pragma unroll
        for (int r = 0; r < 2; r++) {
            int s = tid + 256 * r;
            int row = s >> 2;
            int fq = s & 3;
            int grow = rowBase + row;
            uint4 vh = make_uint4(0, 0, 0, 0), vl = make_uint4(0, 0, 0, 0);
            if (grow < M) {
                size_t ab = (size_t)grow * KP + kp0 + fq * 4;
                vh = *reinterpret_cast<const uint4*>(AH + ab);
                vl = *reinterpret_cast<const uint4*>(AL + ab);
            }
            *reinterpret_cast<uint4*>(&AsH[row][fq * 4]) = vh;
            *reinterpret_cast<uint4*>(&AsL[row][fq * 4]) = vl;
            size_t bb = (size_t)(colBase + row) * KP + kp0 + fq * 4;
            *reinterpret_cast<uint4*>(&BsH[row][fq * 4]) =
                *reinterpret_cast<const uint4*>(WH + bb);
            *reinterpret_cast<uint4*>(&BsL[row][fq * 4]) =
                *reinterpret_cast<const uint4*>(WL + bb);
        }
        __syncthreads();

        #pragma unroll
        for (int ks = 0; ks < 2; ks++) {
            int base = ks * 8;
            uint32_t bh[4][2], bl[4][2];
            #pragma unroll
            for (int nfp = 0; nfp < 2; nfp++) {
                uint32_t off = ((uint32_t)(bRow + nfp * 16) * LDU + base + bCol) * 4;
                uint32_t rh[4], rl[4];
                ldmx4(rh, bH_b + off);
                ldmx4(rl, bL_b + off);
                bh[2 * nfp][0] = rh[0]; bh[2 * nfp][1] = rh[1];
                bh[2 * nfp + 1][0] = rh[2]; bh[2 * nfp + 1][1] = rh[3];
                bl[2 * nfp][0] = rl[0]; bl[2 * nfp][1] = rl[1];
                bl[2 * nfp + 1][0] = rl[2]; bl[2 * nfp + 1][1] = rl[3];
            }
            #pragma unroll
            for (int mf = 0; mf < 4; mf++) {
                uint32_t off = ((uint32_t)(aRow + mf * 16) * LDU + base + aCol) * 4;
                uint32_t ah[4], al[4];
                ldmx4(ah, aH_b + off);
                ldmx4(al, aL_b + off);
                #pragma unroll
                for (int nf = 0; nf < 4; nf++) {
                    mma_bf16(d[mf][nf], ah, bh[nf]);   // hi*hi
                    mma_bf16(d[mf][nf], ah, bl[nf]);   // hi*lo
                    mma_bf16(d[mf][nf], al, bh[nf]);   // lo*hi
                }
            }
        }
        __syncthreads();
    }

    // --- epilogue ---
    #pragma unroll
    for (int nf = 0; nf < 4; nf++) {
        int col = colBase + wn * 32 + nf * 8 + tig * 2;
        int lcol = wn * 32 + nf * 8 + tig * 2;
        float b0 = __ldg(&bias[col]);
        float b1 = __ldg(&bias[col + 1]);
        float s0 = 0.f, q0 = 0.f, s1 = 0.f, q1 = 0.f;
        #pragma unroll
        for (int mf = 0; mf < 4; mf++) {
            int row = rowBase + wm * 64 + mf * 16 + gid;
            if (row < M) {
                float v0 = d[mf][nf][0] + b0;
                float v1 = d[mf][nf][1] + b1;
                if (SEL == 0) {
                    v0 = fmaxf(v0, 0.f); v1 = fmaxf(v1, 0.f);
                    uint32_t hi, lo;
                    split_pair(v0, v1, hi, lo);
                    size_t p = (size_t)row * (NC / 2) + (col >> 1);
                    g_hmidH[p] = hi; g_hmidL[p] = lo;
                } else {
                    g_h2[(size_t)row * NC + col] = v0;
                    g_h2[(size_t)row * NC + col + 1] = v1;
                    s0 += v0; q0 += v0 * v0; s1 += v1; q1 += v1 * v1;
                }
            }
            if (row + 8 < M) {
                float v2 = d[mf][nf][2] + b0;
                float v3 = d[mf][nf][3] + b1;
                if (SEL == 0) {
                    v2 = fmaxf(v2, 0.f); v3 = fmaxf(v3, 0.f);
                    uint32_t hi, lo;
                    split_pair(v2, v3, hi, lo);
                    size_t p = (size_t)(row + 8) * (NC / 2) + (col >> 1);
                    g_hmidH[p] = hi; g_hmidL[p] = lo;
                } else {
                    g_h2[(size_t)(row + 8) * NC + col] = v2;
                    g_h2[(size_t)(row + 8) * NC + col + 1] = v3;
                    s0 += v2; q0 += v2 * v2; s1 += v3; q1 += v3 * v3;
                }
            }
        }
        if (SEL == 1) {
            atomicAdd(&sSum[lcol], s0); atomicAdd(&sSq[lcol], q0);
            atomicAdd(&sSum[lcol + 1], s1); atomicAdd(&sSq[lcol + 1], q1);
        }
    }
    if (SEL == 1) {
        __syncthreads();
        if (tid < BN) {
            atomicAdd(&g_stats[colBase + tid], sSum[tid]);
            atomicAdd(&g_stats[EMB + colBase + tid], sSq[tid]);
        }
    }
}

// ----------------------------------------------------------------------------
__global__ void bn_finalize_kernel(const float* __restrict__ bn_w, const float* __restrict__ bn_b) {
    int c = threadIdx.x;
    if (c >= EMB) return;
    float invN = 1.0f / (float)NN_NODES;
    float mean = g_stats[c] * invN;
    float var = g_stats[EMB + c] * invN - mean * mean;
    float sc = bn_w[c] * rsqrtf(var + BN_EPS);
    g_scale[c] = sc;
    g_shift[c] = bn_b[c] - mean * sc;
}

// ----------------------------------------------------------------------------
// Final output only: out = h2 * scale + shift (no relu on last layer).
// ----------------------------------------------------------------------------
__global__ void bn_apply_kernel(float* __restrict__ out_ext) {
    int t = blockIdx.x * blockDim.x + threadIdx.x;
    if (t >= NN_NODES * (EMB / 4)) return;
    int q = t & 63;
    float4 v = reinterpret_cast<const float4*>(g_h2)[t];
    float4 sc = reinterpret_cast<const float4*>(g_scale)[q];
    float4 sh = reinterpret_cast<const float4*>(g_shift)[q];
    v.x = v.x * sc.x + sh.x;
    v.y = v.y * sc.y + sh.y;
    v.z = v.z * sc.z + sh.z;
    v.w = v.w * sc.w + sh.w;
    reinterpret_cast<float4*>(out_ext)[t] = v;
}

// ----------------------------------------------------------------------------
extern "C" void kernel_launch(void* const* d_in, const int* in_sizes, int n_in,
                              void* d_out, int out_size) {
    const int*   x_atom    = (const int*)d_in[0];
    const int*   x_chir    = (const int*)d_in[1];
    const int*   edge_idx  = (const int*)d_in[2];    // [2,E]
    const int*   edge_bond = (const int*)d_in[3];
    const int*   edge_dir  = (const int*)d_in[4];
    const float* atom_emb  = (const float*)d_in[5];  // [120,256]
    const float* chir_emb  = (const float*)d_in[6];  // [3,256]
    const float* bond_embs = (const float*)d_in[7];  // [5,6,256]
    const float* dir_embs  = (const float*)d_in[8];  // [5,3,256]
    const float* W1s       = (const float*)d_in[9];  // [5,512,256]
    const float* b1s       = (const float*)d_in[10]; // [5,512]
    const float* W2s       = (const float*)d_in[11]; // [5,256,512]
    const float* b2s       = (const float*)d_in[12]; // [5,256]
    const float* bn_w      = (const float*)d_in[13]; // [5,256]
    const float* bn_b      = (const float*)d_in[14]; // [5,256]
    float* out = (float*)d_out;

    const int* src = edge_idx;
    const int* dst = edge_idx + EE_EDGES;

    // --- preprocessing ---
    zero_scratch_kernel<<<512, 256>>>();
    hist_kernel<<<cdiv(EE_EDGES, 256), 256>>>(src, dst, edge_bond, edge_dir);
    scan_kernel<<<1, 1024>>>();
    fill_kernel<<<cdiv(EE_EDGES, 256), 256>>>(src, dst);
    init_h_kernel<<<cdiv(NN_NODES * (EMB / 4), 256), 256>>>(x_atom, x_chir, atom_emb, chir_emb);
    split_w_kernel<<<cdiv(2 * NUM_LAYER * 512 * 128, 256), 256>>>(W1s, W2s);

    dim3 g1(cdiv(NN_NODES, 128), 2 * EMB / 128);  // 782 x 4
    dim3 g2(cdiv(NN_NODES, 128), EMB / 128);      // 782 x 2
    int aggBlocks = cdiv(NN_NODES, 8);
    int applyBlocks = cdiv(NN_NODES * (EMB / 4), 256);

    for (int l = 0; l < NUM_LAYER; l++) {
        const float* BE = bond_embs + (size_t)l * 6 * EMB;
        const float* DE = dir_embs + (size_t)l * 3 * EMB;
        const float* B1 = b1s + (size_t)l * 2 * EMB;
        const float* B2 = b2s + (size_t)l * EMB;

        agg_kernel<<<aggBlocks, 256>>>(BE, DE, l == 0 ? 0 : 1);
        gemm_tc_kernel<0><<<g1, 256>>>(B1, l);      // hmid = relu(agg@W1^T+b1), split out
        zero_stats_kernel<<<1, 512>>>();
        gemm_tc_kernel<1><<<g2, 256>>>(B2, l);      // h2 = hmid@W2^T+b2 (+stats)
        bn_finalize_kernel<<<1, 256>>>(bn_w + l * EMB, bn_b + l * EMB);
    }
    bn_apply_kernel<<<applyBlocks, 256>>>(out);     // final: affine only, to d_out
}

// round 9
// speedup vs baseline: 2.2612x; 1.0855x over previous
#include <cuda_runtime.h>
#include <cuda_bf16.h>
#include <cstdint>

#define NN_NODES 100000
#define EE_EDGES 300000
#define EMB 256
#define NUM_LAYER 5
#define BN_EPS 1e-5f

static inline int cdiv(int a, int b) { return (a + b - 1) / b; }

// ----------------------------------------------------------------------------
// Device scratch. Symbols only referenced from device code.
// Split-bf16: pair (k,k+1) packed bf16x2 in u32; value = hi + lo.
// ----------------------------------------------------------------------------
__device__ float    g_h   [(size_t)NN_NODES * EMB];          // layer-0 node features
__device__ float    g_h2  [(size_t)NN_NODES * EMB];          // MLP out pre-BN (fp32)
__device__ uint32_t g_aggH[(size_t)NN_NODES * (EMB / 2)];
__device__ uint32_t g_aggL[(size_t)NN_NODES * (EMB / 2)];
__device__ uint32_t g_hmidH[(size_t)NN_NODES * EMB];
__device__ uint32_t g_hmidL[(size_t)NN_NODES * EMB];
__device__ uint32_t g_w1H[NUM_LAYER * 512 * 128];
__device__ uint32_t g_w1L[NUM_LAYER * 512 * 128];
__device__ uint32_t g_w2H[NUM_LAYER * 256 * 256];
__device__ uint32_t g_w2L[NUM_LAYER * 256 * 256];

__device__ int   g_indeg[NN_NODES];
__device__ int   g_off  [NN_NODES];
__device__ int   g_ctr  [NN_NODES];
__device__ int   g_adj  [EE_EDGES];
__device__ int   g_cntb [NN_NODES * 4];
__device__ int   g_cntd [NN_NODES * 4];
__device__ float g_stats[2 * EMB];
__device__ float g_scale[EMB];
__device__ float g_shift[EMB];

// ----------------------------------------------------------------------------
__device__ __forceinline__ uint32_t pack2bf(float a, float b) {
    __nv_bfloat162 t = __floats2bfloat162_rn(a, b);
    return *reinterpret_cast<uint32_t*>(&t);
}

__device__ __forceinline__ void split_pair(float a, float b, uint32_t& hi, uint32_t& lo) {
    __nv_bfloat16 ha = __float2bfloat16_rn(a);
    __nv_bfloat16 hb = __float2bfloat16_rn(b);
    __nv_bfloat162 h; h.x = ha; h.y = hb;
    hi = *reinterpret_cast<uint32_t*>(&h);
    lo = pack2bf(a - __bfloat162float(ha), b - __bfloat162float(hb));
}

// ----------------------------------------------------------------------------
__global__ void zero_scratch_kernel() {
    int t = blockIdx.x * blockDim.x + threadIdx.x;
    int stride = gridDim.x * blockDim.x;
    for (int i = t; i < NN_NODES; i += stride) { g_indeg[i] = 0; g_ctr[i] = 0; }
    for (int i = t; i < NN_NODES * 4; i += stride) { g_cntb[i] = 0; g_cntd[i] = 0; }
}

__global__ void zero_stats_kernel() {
    if (threadIdx.x < 2 * EMB) g_stats[threadIdx.x] = 0.0f;
}

// ----------------------------------------------------------------------------
__global__ void split_w_kernel(const float* __restrict__ W1s, const float* __restrict__ W2s) {
    constexpr int NP = NUM_LAYER * 512 * 128;
    int t = blockIdx.x * blockDim.x + threadIdx.x;
    if (t < NP) {
        uint32_t hi, lo;
        split_pair(W1s[2 * t], W1s[2 * t + 1], hi, lo);
        g_w1H[t] = hi; g_w1L[t] = lo;
    } else if (t < 2 * NP) {
        int u = t - NP;
        uint32_t hi, lo;
        split_pair(W2s[2 * u], W2s[2 * u + 1], hi, lo);
        g_w2H[u] = hi; g_w2L[u] = lo;
    }
}

// ----------------------------------------------------------------------------
__global__ void hist_kernel(const int* __restrict__ src, const int* __restrict__ dst,
                            const int* __restrict__ bond, const int* __restrict__ dir) {
    int e = blockIdx.x * blockDim.x + threadIdx.x;
    if (e >= EE_EDGES) return;
    int d = dst[e];
    atomicAdd(&g_indeg[d], 1);
    atomicAdd(&g_cntb[d * 4 + bond[e]], 1);
    atomicAdd(&g_cntd[d * 4 + dir[e]], 1);
}

// ----------------------------------------------------------------------------
__global__ void scan_kernel() {
    __shared__ int s[1024];
    __shared__ int carry;
    int t = threadIdx.x;
    if (t == 0) carry = 0;
    __syncthreads();
    for (int base = 0; base < NN_NODES; base += 1024) {
        int i = base + t;
        int v = (i < NN_NODES) ? g_indeg[i] : 0;
        s[t] = v;
        __syncthreads();
        #pragma unroll
        for (int off = 1; off < 1024; off <<= 1) {
            int x = (t >= off) ? s[t - off] : 0;
            __syncthreads();
            s[t] += x;
            __syncthreads();
        }
        int incl = s[t];
        int c = carry;
        if (i < NN_NODES) g_off[i] = c + incl - v;
        __syncthreads();
        if (t == 1023) carry = c + s[1023];
        __syncthreads();
    }
}

// ----------------------------------------------------------------------------
__global__ void fill_kernel(const int* __restrict__ src, const int* __restrict__ dst) {
    int e = blockIdx.x * blockDim.x + threadIdx.x;
    if (e >= EE_EDGES) return;
    int d = dst[e];
    int p = atomicAdd(&g_ctr[d], 1);
    g_adj[g_off[d] + p] = src[e];
}

// ----------------------------------------------------------------------------
__global__ void init_h_kernel(const int* __restrict__ x_atom, const int* __restrict__ x_chir,
                              const float* __restrict__ atom_emb, const float* __restrict__ chir_emb) {
    int t = blockIdx.x * blockDim.x + threadIdx.x;
    if (t >= NN_NODES * (EMB / 4)) return;
    int row = t >> 6;
    int q = t & 63;
    int a = x_atom[row];
    int c = x_chir[row];
    float4 va = reinterpret_cast<const float4*>(atom_emb)[a * 64 + q];
    float4 vc = reinterpret_cast<const float4*>(chir_emb)[c * 64 + q];
    float4 o;
    o.x = va.x + vc.x; o.y = va.y + vc.y; o.z = va.z + vc.z; o.w = va.w + vc.w;
    reinterpret_cast<float4*>(g_h)[t] = o;
}

// ----------------------------------------------------------------------------
// Aggregation (one warp/node) with BN+ReLU fused on the INPUT side:
//   mode 0: rows come from g_h (layer 0 features, raw)
//   mode 1: rows come from g_h2 with v = relu(v*scale[c]+shift[c]) applied
// Writes split-bf16 output for GEMM1.
// ----------------------------------------------------------------------------
__global__ void agg_kernel(const float* __restrict__ bondE,   // 6x256 (rows 0..4 used)
                           const float* __restrict__ dirE,    // 3x256
                           int mode) {
    __shared__ float sBE[5 * EMB];
    __shared__ float sDE[3 * EMB];
    int tid = threadIdx.x;
    for (int i = tid; i < 5 * EMB; i += 256) sBE[i] = bondE[i];
    for (int i = tid; i < 3 * EMB; i += 256) sDE[i] = dirE[i];
    __syncthreads();

    int warp = tid >> 5, lane = tid & 31;
    int node = blockIdx.x * 8 + warp;
    if (node >= NN_NODES) return;
    int c0 = lane * 8;

    float sc[8], sh[8];
    {
        float4 s0 = *reinterpret_cast<const float4*>(g_scale + c0);
        float4 s1 = *reinterpret_cast<const float4*>(g_scale + c0 + 4);
        float4 h0 = *reinterpret_cast<const float4*>(g_shift + c0);
        float4 h1 = *reinterpret_cast<const float4*>(g_shift + c0 + 4);
        sc[0] = s0.x; sc[1] = s0.y; sc[2] = s0.z; sc[3] = s0.w;
        sc[4] = s1.x; sc[5] = s1.y; sc[6] = s1.z; sc[7] = s1.w;
        sh[0] = h0.x; sh[1] = h0.y; sh[2] = h0.z; sh[3] = h0.w;
        sh[4] = h1.x; sh[5] = h1.y; sh[6] = h1.z; sh[7] = h1.w;
    }

    const float* __restrict__ H = (mode == 0) ? g_h : g_h2;

    float acc[8];
    {   // self row
        const float4* hrow = reinterpret_cast<const float4*>(H + (size_t)node * EMB + c0);
        float4 a0 = hrow[0], a1 = hrow[1];
        float raw[8] = {a0.x, a0.y, a0.z, a0.w, a1.x, a1.y, a1.z, a1.w};
        #pragma unroll
        for (int c = 0; c < 8; c++)
            acc[c] = (mode == 0) ? raw[c] : fmaxf(fmaf(raw[c], sc[c], sh[c]), 0.f);
    }

    float fb0 = (float)g_cntb[node * 4 + 0];
    float fb1 = (float)g_cntb[node * 4 + 1];
    float fb2 = (float)g_cntb[node * 4 + 2];
    float fb3 = (float)g_cntb[node * 4 + 3];
    float fd0 = (float)g_cntd[node * 4 + 0] + 1.0f;   // + self loop dir 0
    float fd1 = (float)g_cntd[node * 4 + 1];
    float fd2 = (float)g_cntd[node * 4 + 2];

    #pragma unroll
    for (int c = 0; c < 8; c++) {
        int cc = c0 + c;
        float v = sBE[4 * EMB + cc];                  // self loop bond 4
        v += fb0 * sBE[0 * EMB + cc] + fb1 * sBE[1 * EMB + cc]
           + fb2 * sBE[2 * EMB + cc] + fb3 * sBE[3 * EMB + cc];
        v += fd0 * sDE[0 * EMB + cc] + fd1 * sDE[1 * EMB + cc] + fd2 * sDE[2 * EMB + cc];
        acc[c] += v;
    }

    int s = g_off[node];
    int deg = g_indeg[node];
    for (int e = s; e < s + deg; e++) {
        int j = __ldg(&g_adj[e]);
        const float4* hj = reinterpret_cast<const float4*>(H + (size_t)j * EMB + c0);
        float4 b0 = hj[0], b1 = hj[1];
        float raw[8] = {b0.x, b0.y, b0.z, b0.w, b1.x, b1.y, b1.z, b1.w};
        if (mode == 0) {
            #pragma unroll
            for (int c = 0; c < 8; c++) acc[c] += raw[c];
        } else {
            #pragma unroll
            for (int c = 0; c < 8; c++)
                acc[c] += fmaxf(fmaf(raw[c], sc[c], sh[c]), 0.f);
        }
    }

    uint4 hv, lv;
    split_pair(acc[0], acc[1], hv.x, lv.x);
    split_pair(acc[2], acc[3], hv.y, lv.y);
    split_pair(acc[4], acc[5], hv.z, lv.z);
    split_pair(acc[6], acc[7], hv.w, lv.w);
    size_t base = (size_t)node * (EMB / 2) + lane * 4;
    *reinterpret_cast<uint4*>(&g_aggH[base]) = hv;
    *reinterpret_cast<uint4*>(&g_aggL[base]) = lv;
}

// ----------------------------------------------------------------------------
// Split-BF16 tensor-core GEMM: cp.async double-buffered, ldmatrix frags.
//   D += Ahi*Bhi + Ahi*Blo + Alo*Bhi   (m16n8k16.bf16)
// Block 128x128, BK=32 elements (16 pairs), 8 warps (2x4), 2-stage pipeline.
// Dynamic smem: 2 stages x 4 arrays x [128][20] u32 = 81920 B.
//   SEL=0: A=g_agg (K=256) -> g_hmid split + ReLU (NC=512)
//   SEL=1: A=g_hmid (K=512) -> g_h2 fp32 + BN stats (NC=256)
// ----------------------------------------------------------------------------
__device__ __forceinline__ void mma_bf16(float d[4], const uint32_t a[4], const uint32_t b[2]) {
    asm volatile(
        "mma.sync.aligned.m16n8k16.row.col.f32.bf16.bf16.f32 "
        "{%0,%1,%2,%3}, {%4,%5,%6,%7}, {%8,%9}, {%0,%1,%2,%3};"
        : "+f"(d[0]), "+f"(d[1]), "+f"(d[2]), "+f"(d[3])
        : "r"(a[0]), "r"(a[1]), "r"(a[2]), "r"(a[3]), "r"(b[0]), "r"(b[1]));
}

__device__ __forceinline__ void ldmx4(uint32_t* r, uint32_t addr) {
    asm volatile("ldmatrix.sync.aligned.m8n8.x4.shared.b16 {%0,%1,%2,%3}, [%4];"
                 : "=r"(r[0]), "=r"(r[1]), "=r"(r[2]), "=r"(r[3]) : "r"(addr));
}

__device__ __forceinline__ void cpa16(uint32_t dst, const void* src, int szbytes) {
    asm volatile("cp.async.cg.shared.global [%0], [%1], 16, %2;"
                 :: "r"(dst), "l"(src), "r"(szbytes));
}

template <int SEL>
__global__ void __launch_bounds__(256)
gemm_tc_kernel(const float* __restrict__ bias, int layer) {
    constexpr int M = NN_NODES;
    constexpr int K = (SEL == 0) ? EMB : 2 * EMB;
    constexpr int NC = (SEL == 0) ? 2 * EMB : EMB;
    constexpr int KP = K / 2;
    const uint32_t* __restrict__ AH = (SEL == 0) ? g_aggH : g_hmidH;
    const uint32_t* __restrict__ AL = (SEL == 0) ? g_aggL : g_hmidL;
    const uint32_t* __restrict__ WH = ((SEL == 0) ? g_w1H : g_w2H) + (size_t)layer * NC * KP;
    const uint32_t* __restrict__ WL = ((SEL == 0) ? g_w1L : g_w2L) + (size_t)layer * NC * KP;

    constexpr int BM = 128, BN = 128;
    constexpr int BKP = 16;              // pairs per K-tile
    constexpr int LDU = BKP + 4;         // stride 20 u32: ldmatrix conflict-free
    constexpr int AR = BM * LDU;         // 2560 u32 per array
    constexpr int STG = 4 * AR;          // u32 per stage
    constexpr int NT = KP / BKP;         // K tiles

    extern __shared__ uint32_t dsm[];
    __shared__ float sSum[BN];
    __shared__ float sSq[BN];
    uint32_t sbase = (uint32_t)__cvta_generic_to_shared(dsm);

    int tid = threadIdx.x;
    int wid = tid >> 5, lane = tid & 31;
    int wm = wid & 1;
    int wn = wid >> 1;
    int rowBase = blockIdx.x * BM;
    int colBase = blockIdx.y * BN;

    if (SEL == 1 && tid < BN) { sSum[tid] = 0.f; sSq[tid] = 0.f; }

    float d[4][4][4];
    #pragma unroll
    for (int i = 0; i < 4; i++)
        #pragma unroll
        for (int j = 0; j < 4; j++)
            #pragma unroll
            for (int r = 0; r < 4; r++) d[i][j][r] = 0.0f;

    int gid = lane >> 2;
    int tig = lane & 3;

    // staging coordinates (per thread): 2 chunks of 16B per array per tile
    int srow0 = tid >> 2;               // chunk 0: rows 0..63
    int sfq0 = tid & 3;
    int srow1 = (tid + 256) >> 2;       // chunk 1: rows 64..127
    int sfq1 = sfq0;

    // ldmatrix lane-address components
    int aRow = wm * 64 + (lane & 15);
    int aCol = (lane >> 4) * 4;
    int bRow = wn * 32 + (lane & 7) + ((lane >> 4) << 3);
    int bCol = ((lane >> 3) & 1) * 4;

    auto prefetch = [&](int t, int s) {
        int kp0 = t * BKP;
        uint32_t sb = sbase + (uint32_t)(s * STG) * 4;
        #pragma unroll
        for (int r = 0; r < 2; r++) {
            int row = (r == 0) ? srow0 : srow1;
            int fq = (r == 0) ? sfq0 : sfq1;
            uint32_t doff = (uint32_t)(row * LDU + fq * 4) * 4;
            int grow = rowBase + row;
            size_t ab = (size_t)grow * KP + kp0 + fq * 4;
            int sz = (grow < M) ? 16 : 0;
            cpa16(sb + 0 * AR * 4 + doff, AH + ab, sz);
            cpa16(sb + 1 * AR * 4 + doff, AL + ab, sz);
            size_t bb = (size_t)(colBase + row) * KP + kp0 + fq * 4;
            cpa16(sb + 2 * AR * 4 + doff, WH + bb, 16);
            cpa16(sb + 3 * AR * 4 + doff, WL + bb, 16);
        }
        asm volatile("cp.async.commit_group;");
    };

    prefetch(0, 0);

    for (int t = 0; t < NT; t++) {
        int s = t & 1;
        if (t + 1 < NT) {
            prefetch(t + 1, (t + 1) & 1);
            asm volatile("cp.async.wait_group 1;");
        } else {
            asm volatile("cp.async.wait_group 0;");
        }
        __syncthreads();

        uint32_t aH_b = sbase + (uint32_t)(s * STG + 0 * AR) * 4;
        uint32_t aL_b = sbase + (uint32_t)(s * STG + 1 * AR) * 4;
        uint32_t bH_b = sbase + (uint32_t)(s * STG + 2 * AR) * 4;
        uint32_t bL_b = sbase + (uint32_t)(s * STG + 3 * AR) * 4;

        #pragma unroll
        for (int ks = 0; ks < 2; ks++) {
            int base = ks * 8;
            uint32_t bh[4][2], bl[4][2];
            #pragma unroll
            for (int nfp = 0; nfp < 2; nfp++) {
                uint32_t off = ((uint32_t)(bRow + nfp * 16) * LDU + base + bCol) * 4;
                uint32_t rh[4], rl[4];
                ldmx4(rh, bH_b + off);
                ldmx4(rl, bL_b + off);
                bh[2 * nfp][0] = rh[0]; bh[2 * nfp][1] = rh[1];
                bh[2 * nfp + 1][0] = rh[2]; bh[2 * nfp + 1][1] = rh[3];
                bl[2 * nfp][0] = rl[0]; bl[2 * nfp][1] = rl[1];
                bl[2 * nfp + 1][0] = rl[2]; bl[2 * nfp + 1][1] = rl[3];
            }
            #pragma unroll
            for (int mf = 0; mf < 4; mf++) {
                uint32_t off = ((uint32_t)(aRow + mf * 16) * LDU + base + aCol) * 4;
                uint32_t ah[4], al[4];
                ldmx4(ah, aH_b + off);
                ldmx4(al, aL_b + off);
                #pragma unroll
                for (int nf = 0; nf < 4; nf++) {
                    mma_bf16(d[mf][nf], ah, bh[nf]);   // hi*hi
                    mma_bf16(d[mf][nf], ah, bl[nf]);   // hi*lo
                    mma_bf16(d[mf][nf], al, bh[nf]);   // lo*hi
                }
            }
        }
        __syncthreads();
    }

    // --- epilogue ---
    #pragma unroll
    for (int nf = 0; nf < 4; nf++) {
        int col = colBase + wn * 32 + nf * 8 + tig * 2;
        int lcol = wn * 32 + nf * 8 + tig * 2;
        float b0 = __ldg(&bias[col]);
        float b1 = __ldg(&bias[col + 1]);
        float s0 = 0.f, q0 = 0.f, s1 = 0.f, q1 = 0.f;
        #pragma unroll
        for (int mf = 0; mf < 4; mf++) {
            int row = rowBase + wm * 64 + mf * 16 + gid;
            if (row < M) {
                float v0 = d[mf][nf][0] + b0;
                float v1 = d[mf][nf][1] + b1;
                if (SEL == 0) {
                    v0 = fmaxf(v0, 0.f); v1 = fmaxf(v1, 0.f);
                    uint32_t hi, lo;
                    split_pair(v0, v1, hi, lo);
                    size_t p = (size_t)row * (NC / 2) + (col >> 1);
                    g_hmidH[p] = hi; g_hmidL[p] = lo;
                } else {
                    g_h2[(size_t)row * NC + col] = v0;
                    g_h2[(size_t)row * NC + col + 1] = v1;
                    s0 += v0; q0 += v0 * v0; s1 += v1; q1 += v1 * v1;
                }
            }
            if (row + 8 < M) {
                float v2 = d[mf][nf][2] + b0;
                float v3 = d[mf][nf][3] + b1;
                if (SEL == 0) {
                    v2 = fmaxf(v2, 0.f); v3 = fmaxf(v3, 0.f);
                    uint32_t hi, lo;
                    split_pair(v2, v3, hi, lo);
                    size_t p = (size_t)(row + 8) * (NC / 2) + (col >> 1);
                    g_hmidH[p] = hi; g_hmidL[p] = lo;
                } else {
                    g_h2[(size_t)(row + 8) * NC + col] = v2;
                    g_h2[(size_t)(row + 8) * NC + col + 1] = v3;
                    s0 += v2; q0 += v2 * v2; s1 += v3; q1 += v3 * v3;
                }
            }
        }
        if (SEL == 1) {
            atomicAdd(&sSum[lcol], s0); atomicAdd(&sSq[lcol], q0);
            atomicAdd(&sSum[lcol + 1], s1); atomicAdd(&sSq[lcol + 1], q1);
        }
    }
    if (SEL == 1) {
        __syncthreads();
        if (tid < BN) {
            atomicAdd(&g_stats[colBase + tid], sSum[tid]);
            atomicAdd(&g_stats[EMB + colBase + tid], sSq[tid]);
        }
    }
}

// ----------------------------------------------------------------------------
__global__ void bn_finalize_kernel(const float* __restrict__ bn_w, const float* __restrict__ bn_b) {
    int c = threadIdx.x;
    if (c >= EMB) return;
    float invN = 1.0f / (float)NN_NODES;
    float mean = g_stats[c] * invN;
    float var = g_stats[EMB + c] * invN - mean * mean;
    float sc = bn_w[c] * rsqrtf(var + BN_EPS);
    g_scale[c] = sc;
    g_shift[c] = bn_b[c] - mean * sc;
}

// ----------------------------------------------------------------------------
__global__ void bn_apply_kernel(float* __restrict__ out_ext) {
    int t = blockIdx.x * blockDim.x + threadIdx.x;
    if (t >= NN_NODES * (EMB / 4)) return;
    int q = t & 63;
    float4 v = reinterpret_cast<const float4*>(g_h2)[t];
    float4 sc = reinterpret_cast<const float4*>(g_scale)[q];
    float4 sh = reinterpret_cast<const float4*>(g_shift)[q];
    v.x = v.x * sc.x + sh.x;
    v.y = v.y * sc.y + sh.y;
    v.z = v.z * sc.z + sh.z;
    v.w = v.w * sc.w + sh.w;
    reinterpret_cast<float4*>(out_ext)[t] = v;
}

// ----------------------------------------------------------------------------
extern "C" void kernel_launch(void* const* d_in, const int* in_sizes, int n_in,
                              void* d_out, int out_size) {
    const int*   x_atom    = (const int*)d_in[0];
    const int*   x_chir    = (const int*)d_in[1];
    const int*   edge_idx  = (const int*)d_in[2];    // [2,E]
    const int*   edge_bond = (const int*)d_in[3];
    const int*   edge_dir  = (const int*)d_in[4];
    const float* atom_emb  = (const float*)d_in[5];  // [120,256]
    const float* chir_emb  = (const float*)d_in[6];  // [3,256]
    const float* bond_embs = (const float*)d_in[7];  // [5,6,256]
    const float* dir_embs  = (const float*)d_in[8];  // [5,3,256]
    const float* W1s       = (const float*)d_in[9];  // [5,512,256]
    const float* b1s       = (const float*)d_in[10]; // [5,512]
    const float* W2s       = (const float*)d_in[11]; // [5,256,512]
    const float* b2s       = (const float*)d_in[12]; // [5,256]
    const float* bn_w      = (const float*)d_in[13]; // [5,256]
    const float* bn_b      = (const float*)d_in[14]; // [5,256]
    float* out = (float*)d_out;

    const int* src = edge_idx;
    const int* dst = edge_idx + EE_EDGES;

    const int SMEM_GEMM = 2 * 4 * 128 * 20 * 4;   // 81920 B
    cudaFuncSetAttribute(gemm_tc_kernel<0>, cudaFuncAttributeMaxDynamicSharedMemorySize, SMEM_GEMM);
    cudaFuncSetAttribute(gemm_tc_kernel<1>, cudaFuncAttributeMaxDynamicSharedMemorySize, SMEM_GEMM);

    // --- preprocessing ---
    zero_scratch_kernel<<<512, 256>>>();
    hist_kernel<<<cdiv(EE_EDGES, 256), 256>>>(src, dst, edge_bond, edge_dir);
    scan_kernel<<<1, 1024>>>();
    fill_kernel<<<cdiv(EE_EDGES, 256), 256>>>(src, dst);
    init_h_kernel<<<cdiv(NN_NODES * (EMB / 4), 256), 256>>>(x_atom, x_chir, atom_emb, chir_emb);
    split_w_kernel<<<cdiv(2 * NUM_LAYER * 512 * 128, 256), 256>>>(W1s, W2s);

    dim3 g1(cdiv(NN_NODES, 128), 2 * EMB / 128);  // 782 x 4
    dim3 g2(cdiv(NN_NODES, 128), EMB / 128);      // 782 x 2
    int aggBlocks = cdiv(NN_NODES, 8);
    int applyBlocks = cdiv(NN_NODES * (EMB / 4), 256);

    for (int l = 0; l < NUM_LAYER; l++) {
        const float* BE = bond_embs + (size_t)l * 6 * EMB;
        const float* DE = dir_embs + (size_t)l * 3 * EMB;
        const float* B1 = b1s + (size_t)l * 2 * EMB;
        const float* B2 = b2s + (size_t)l * EMB;

        agg_kernel<<<aggBlocks, 256>>>(BE, DE, l == 0 ? 0 : 1);
        gemm_tc_kernel<0><<<g1, 256, SMEM_GEMM>>>(B1, l);   // hmid = relu(agg@W1^T+b1)
        zero_stats_kernel<<<1, 512>>>();
        gemm_tc_kernel<1><<<g2, 256, SMEM_GEMM>>>(B2, l);   // h2 = hmid@W2^T+b2 (+stats)
        bn_finalize_kernel<<<1, 256>>>(bn_w + l * EMB, bn_b + l * EMB);
    }
    bn_apply_kernel<<<applyBlocks, 256>>>(out);             // final: affine only
}

// round 12
// speedup vs baseline: 2.3767x; 1.0510x over previous
#include <cuda_runtime.h>
#include <cuda_bf16.h>
#include <cstdint>

#define NN_NODES 100000
#define EE_EDGES 300000
#define EMB 256
#define NUM_LAYER 5
#define BN_EPS 1e-5f

static inline int cdiv(int a, int b) { return (a + b - 1) / b; }

// ----------------------------------------------------------------------------
// Device scratch. Symbols only referenced from device code.
// Split-bf16: pair (k,k+1) packed bf16x2 in u32; value = hi + lo.
// ----------------------------------------------------------------------------
__device__ float    g_h   [(size_t)NN_NODES * EMB];          // layer-0 node features
__device__ float    g_h2  [(size_t)NN_NODES * EMB];          // MLP out pre-BN (fp32)
__device__ uint32_t g_aggH[(size_t)NN_NODES * (EMB / 2)];
__device__ uint32_t g_aggL[(size_t)NN_NODES * (EMB / 2)];
__device__ uint32_t g_hmidH[(size_t)NN_NODES * EMB];
__device__ uint32_t g_hmidL[(size_t)NN_NODES * EMB];
__device__ uint32_t g_w1H[NUM_LAYER * 512 * 128];
__device__ uint32_t g_w1L[NUM_LAYER * 512 * 128];
__device__ uint32_t g_w2H[NUM_LAYER * 256 * 256];
__device__ uint32_t g_w2L[NUM_LAYER * 256 * 256];

__device__ int   g_indeg[NN_NODES];
__device__ int   g_off  [NN_NODES];
__device__ int   g_ctr  [NN_NODES];
__device__ int   g_adj  [EE_EDGES];
__device__ int   g_cntb [NN_NODES * 4];
__device__ int   g_cntd [NN_NODES * 4];
__device__ float g_stats[2 * EMB];
__device__ float g_scale[EMB];
__device__ float g_shift[EMB];

// ----------------------------------------------------------------------------
__device__ __forceinline__ uint32_t pack2bf(float a, float b) {
    __nv_bfloat162 t = __floats2bfloat162_rn(a, b);
    return *reinterpret_cast<uint32_t*>(&t);
}

__device__ __forceinline__ void split_pair(float a, float b, uint32_t& hi, uint32_t& lo) {
    __nv_bfloat16 ha = __float2bfloat16_rn(a);
    __nv_bfloat16 hb = __float2bfloat16_rn(b);
    __nv_bfloat162 h; h.x = ha; h.y = hb;
    hi = *reinterpret_cast<uint32_t*>(&h);
    lo = pack2bf(a - __bfloat162float(ha), b - __bfloat162float(hb));
}

// ----------------------------------------------------------------------------
__global__ void zero_scratch_kernel() {
    int t = blockIdx.x * blockDim.x + threadIdx.x;
    int stride = gridDim.x * blockDim.x;
    for (int i = t; i < NN_NODES; i += stride) { g_indeg[i] = 0; g_ctr[i] = 0; }
    for (int i = t; i < NN_NODES * 4; i += stride) { g_cntb[i] = 0; g_cntd[i] = 0; }
}

__global__ void zero_stats_kernel() {
    if (threadIdx.x < 2 * EMB) g_stats[threadIdx.x] = 0.0f;
}

// ----------------------------------------------------------------------------
__global__ void split_w_kernel(const float* __restrict__ W1s, const float* __restrict__ W2s) {
    constexpr int NP = NUM_LAYER * 512 * 128;
    int t = blockIdx.x * blockDim.x + threadIdx.x;
    if (t < NP) {
        uint32_t hi, lo;
        split_pair(W1s[2 * t], W1s[2 * t + 1], hi, lo);
        g_w1H[t] = hi; g_w1L[t] = lo;
    } else if (t < 2 * NP) {
        int u = t - NP;
        uint32_t hi, lo;
        split_pair(W2s[2 * u], W2s[2 * u + 1], hi, lo);
        g_w2H[u] = hi; g_w2L[u] = lo;
    }
}

// ----------------------------------------------------------------------------
__global__ void hist_kernel(const int* __restrict__ src, const int* __restrict__ dst,
                            const int* __restrict__ bond, const int* __restrict__ dir) {
    int e = blockIdx.x * blockDim.x + threadIdx.x;
    if (e >= EE_EDGES) return;
    int d = dst[e];
    atomicAdd(&g_indeg[d], 1);
    atomicAdd(&g_cntb[d * 4 + bond[e]], 1);
    atomicAdd(&g_cntd[d * 4 + dir[e]], 1);
}

// ----------------------------------------------------------------------------
__global__ void scan_kernel() {
    __shared__ int s[1024];
    __shared__ int carry;
    int t = threadIdx.x;
    if (t == 0) carry = 0;
    __syncthreads();
    for (int base = 0; base < NN_NODES; base += 1024) {
        int i = base + t;
        int v = (i < NN_NODES) ? g_indeg[i] : 0;
        s[t] = v;
        __syncthreads();
        #pragma unroll
        for (int off = 1; off < 1024; off <<= 1) {
            int x = (t >= off) ? s[t - off] : 0;
            __syncthreads();
            s[t] += x;
            __syncthreads();
        }
        int incl = s[t];
        int c = carry;
        if (i < NN_NODES) g_off[i] = c + incl - v;
        __syncthreads();
        if (t == 1023) carry = c + s[1023];
        __syncthreads();
    }
}

// ----------------------------------------------------------------------------
__global__ void fill_kernel(const int* __restrict__ src, const int* __restrict__ dst) {
    int e = blockIdx.x * blockDim.x + threadIdx.x;
    if (e >= EE_EDGES) return;
    int d = dst[e];
    int p = atomicAdd(&g_ctr[d], 1);
    g_adj[g_off[d] + p] = src[e];
}

// ----------------------------------------------------------------------------
__global__ void init_h_kernel(const int* __restrict__ x_atom, const int* __restrict__ x_chir,
                              const float* __restrict__ atom_emb, const float* __restrict__ chir_emb) {
    int t = blockIdx.x * blockDim.x + threadIdx.x;
    if (t >= NN_NODES * (EMB / 4)) return;
    int row = t >> 6;
    int q = t & 63;
    int a = x_atom[row];
    int c = x_chir[row];
    float4 va = reinterpret_cast<const float4*>(atom_emb)[a * 64 + q];
    float4 vc = reinterpret_cast<const float4*>(chir_emb)[c * 64 + q];
    float4 o;
    o.x = va.x + vc.x; o.y = va.y + vc.y; o.z = va.z + vc.z; o.w = va.w + vc.w;
    reinterpret_cast<float4*>(g_h)[t] = o;
}

// ----------------------------------------------------------------------------
// Aggregation v2: one warp per node via grid-stride; the 8x8 per-lane slice of
// the bond/dir embedding tables lives in REGISTERS (loaded once per warp,
// amortized over ~21 nodes) -- the previous smem version had 8-way bank
// conflicts on every table read. BN+ReLU fused on the input side (MODE=1).
//   contribution[c] = (BE4+DE0)[c] + sum_b cntb*BE_b[c] + sum_d cntd*DE_d[c]
// Writes split-bf16 output for GEMM1.
// ----------------------------------------------------------------------------
template <int MODE>
__global__ void __launch_bounds__(256)
agg_kernel(const float* __restrict__ bondE,   // 6x256 (rows 0..4 used)
           const float* __restrict__ dirE) {  // 3x256
    int tid = threadIdx.x;
    int lane = tid & 31;
    int warpG = blockIdx.x * 8 + (tid >> 5);
    int nWarps = gridDim.x * 8;
    int c0 = lane * 8;

    // per-lane register tables: base = BE4 + DE0, plus BE0..3, DE0..2
    float base[8], tB0[8], tB1[8], tB2[8], tB3[8], tD0[8], tD1[8], tD2[8];
    #pragma unroll
    for (int c = 0; c < 8; c++) {
        int cc = c0 + c;
        tB0[c] = __ldg(&bondE[0 * EMB + cc]);
        tB1[c] = __ldg(&bondE[1 * EMB + cc]);
        tB2[c] = __ldg(&bondE[2 * EMB + cc]);
        tB3[c] = __ldg(&bondE[3 * EMB + cc]);
        tD0[c] = __ldg(&dirE[0 * EMB + cc]);
        tD1[c] = __ldg(&dirE[1 * EMB + cc]);
        tD2[c] = __ldg(&dirE[2 * EMB + cc]);
        base[c] = __ldg(&bondE[4 * EMB + cc]) + tD0[c];
    }

    float sc[8], sh[8];
    if (MODE == 1) {
        #pragma unroll
        for (int c = 0; c < 8; c++) {
            sc[c] = __ldg(&g_scale[c0 + c]);
            sh[c] = __ldg(&g_shift[c0 + c]);
        }
    }

    const float* __restrict__ H = (MODE == 0) ? g_h : g_h2;

    for (int node = warpG; node < NN_NODES; node += nWarps) {
        int4 cb = *reinterpret_cast<const int4*>(&g_cntb[node * 4]);
        int4 cd = *reinterpret_cast<const int4*>(&g_cntd[node * 4]);
        float fb0 = (float)cb.x, fb1 = (float)cb.y, fb2 = (float)cb.z, fb3 = (float)cb.w;
        float fd0 = (float)cd.x, fd1 = (float)cd.y, fd2 = (float)cd.z;

        float acc[8];
        #pragma unroll
        for (int c = 0; c < 8; c++) {
            float v = base[c];
            v = fmaf(fb0, tB0[c], v);
            v = fmaf(fb1, tB1[c], v);
            v = fmaf(fb2, tB2[c], v);
            v = fmaf(fb3, tB3[c], v);
            v = fmaf(fd0, tD0[c], v);
            v = fmaf(fd1, tD1[c], v);
            v = fmaf(fd2, tD2[c], v);
            acc[c] = v;
        }

        {   // self row
            const float4* hrow = reinterpret_cast<const float4*>(H + (size_t)node * EMB + c0);
            float4 a0 = hrow[0], a1 = hrow[1];
            float raw[8] = {a0.x, a0.y, a0.z, a0.w, a1.x, a1.y, a1.z, a1.w};
            #pragma unroll
            for (int c = 0; c < 8; c++)
                acc[c] += (MODE == 0) ? raw[c] : fmaxf(fmaf(raw[c], sc[c], sh[c]), 0.f);
        }

        int s = g_off[node];
        int eEnd = s + g_indeg[node];
        int e = s;
        for (; e + 2 <= eEnd; e += 2) {
            int j0 = __ldg(&g_adj[e]);
            int j1 = __ldg(&g_adj[e + 1]);
            const float4* h0 = reinterpret_cast<const float4*>(H + (size_t)j0 * EMB + c0);
            const float4* h1 = reinterpret_cast<const float4*>(H + (size_t)j1 * EMB + c0);
            float4 a0 = h0[0], a1 = h0[1], b0 = h1[0], b1 = h1[1];
            float r0[8] = {a0.x, a0.y, a0.z, a0.w, a1.x, a1.y, a1.z, a1.w};
            float r1[8] = {b0.x, b0.y, b0.z, b0.w, b1.x, b1.y, b1.z, b1.w};
            if (MODE == 0) {
                #pragma unroll
                for (int c = 0; c < 8; c++) acc[c] += r0[c] + r1[c];
            } else {
                #pragma unroll
                for (int c = 0; c < 8; c++) {
                    acc[c] += fmaxf(fmaf(r0[c], sc[c], sh[c]), 0.f);
                    acc[c] += fmaxf(fmaf(r1[c], sc[c], sh[c]), 0.f);
                }
            }
        }
        if (e < eEnd) {
            int j = __ldg(&g_adj[e]);
            const float4* hj = reinterpret_cast<const float4*>(H + (size_t)j * EMB + c0);
            float4 b0 = hj[0], b1 = hj[1];
            float raw[8] = {b0.x, b0.y, b0.z, b0.w, b1.x, b1.y, b1.z, b1.w};
            #pragma unroll
            for (int c = 0; c < 8; c++)
                acc[c] += (MODE == 0) ? raw[c] : fmaxf(fmaf(raw[c], sc[c], sh[c]), 0.f);
        }

        uint4 hv, lv;
        split_pair(acc[0], acc[1], hv.x, lv.x);
        split_pair(acc[2], acc[3], hv.y, lv.y);
        split_pair(acc[4], acc[5], hv.z, lv.z);
        split_pair(acc[6], acc[7], hv.w, lv.w);
        size_t obase = (size_t)node * (EMB / 2) + lane * 4;
        *reinterpret_cast<uint4*>(&g_aggH[obase]) = hv;
        *reinterpret_cast<uint4*>(&g_aggL[obase]) = lv;
    }
}

// ----------------------------------------------------------------------------
// Split-BF16 tensor-core GEMM: cp.async double-buffered, ldmatrix frags.
//   D += Ahi*Bhi + Ahi*Blo + Alo*Bhi   (m16n8k16.bf16)
// Block 128x128, BK=32 elements (16 pairs), 8 warps (2x4), 2-stage pipeline.
//   SEL=0: A=g_agg (K=256) -> g_hmid split + ReLU (NC=512)
//   SEL=1: A=g_hmid (K=512) -> g_h2 fp32 + BN stats (NC=256)
// ----------------------------------------------------------------------------
__device__ __forceinline__ void mma_bf16(float d[4], const uint32_t a[4], const uint32_t b[2]) {
    asm volatile(
        "mma.sync.aligned.m16n8k16.row.col.f32.bf16.bf16.f32 "
        "{%0,%1,%2,%3}, {%4,%5,%6,%7}, {%8,%9}, {%0,%1,%2,%3};"
        : "+f"(d[0]), "+f"(d[1]), "+f"(d[2]), "+f"(d[3])
        : "r"(a[0]), "r"(a[1]), "r"(a[2]), "r"(a[3]), "r"(b[0]), "r"(b[1]));
}

__device__ __forceinline__ void ldmx4(uint32_t* r, uint32_t addr) {
    asm volatile("ldmatrix.sync.aligned.m8n8.x4.shared.b16 {%0,%1,%2,%3}, [%4];"
                 : "=r"(r[0]), "=r"(r[1]), "=r"(r[2]), "=r"(r[3]) : "r"(addr));
}

__device__ __forceinline__ void cpa16(uint32_t dst, const void* src, int szbytes) {
    asm volatile("cp.async.cg.shared.global [%0], [%1], 16, %2;"
                 :: "r"(dst), "l"(src), "r"(szbytes));
}

template <int SEL>
__global__ void __launch_bounds__(256)
gemm_tc_kernel(const float* __restrict__ bias, int layer) {
    constexpr int M = NN_NODES;
    constexpr int K = (SEL == 0) ? EMB : 2 * EMB;
    constexpr int NC = (SEL == 0) ? 2 * EMB : EMB;
    constexpr int KP = K / 2;
    const uint32_t* __restrict__ AH = (SEL == 0) ? g_aggH : g_hmidH;
    const uint32_t* __restrict__ AL = (SEL == 0) ? g_aggL : g_hmidL;
    const uint32_t* __restrict__ WH = ((SEL == 0) ? g_w1H : g_w2H) + (size_t)layer * NC * KP;
    const uint32_t* __restrict__ WL = ((SEL == 0) ? g_w1L : g_w2L) + (size_t)layer * NC * KP;

    constexpr int BM = 128, BN = 128;
    constexpr int BKP = 16;              // pairs per K-tile
    constexpr int LDU = BKP + 4;         // stride 20 u32: ldmatrix conflict-free
    constexpr int AR = BM * LDU;         // 2560 u32 per array
    constexpr int STG = 4 * AR;          // u32 per stage
    constexpr int NT = KP / BKP;         // K tiles

    extern __shared__ uint32_t dsm[];
    __shared__ float sSum[BN];
    __shared__ float sSq[BN];
    uint32_t sbase = (uint32_t)__cvta_generic_to_shared(dsm);

    int tid = threadIdx.x;
    int wid = tid >> 5, lane = tid & 31;
    int wm = wid & 1;
    int wn = wid >> 1;
    int rowBase = blockIdx.x * BM;
    int colBase = blockIdx.y * BN;

    if (SEL == 1 && tid < BN) { sSum[tid] = 0.f; sSq[tid] = 0.f; }

    float d[4][4][4];
    #pragma unroll
    for (int i = 0; i < 4; i++)
        #pragma unroll
        for (int j = 0; j < 4; j++)
            #pragma unroll
            for (int r = 0; r < 4; r++) d[i][j][r] = 0.0f;

    int gid = lane >> 2;
    int tig = lane & 3;

    // staging coordinates (per thread): 2 chunks of 16B per array per tile
    int srow0 = tid >> 2;
    int sfq0 = tid & 3;
    int srow1 = (tid + 256) >> 2;
    int sfq1 = sfq0;

    // ldmatrix lane-address components
    int aRow = wm * 64 + (lane & 15);
    int aCol = (lane >> 4) * 4;
    int bRow = wn * 32 + (lane & 7) + ((lane >> 4) << 3);
    int bCol = ((lane >> 3) & 1) * 4;

    auto prefetch = [&](int t, int s) {
        int kp0 = t * BKP;
        uint32_t sb = sbase + (uint32_t)(s * STG) * 4;
        #pragma unroll
        for (int r = 0; r < 2; r++) {
            int row = (r == 0) ? srow0 : srow1;
            int fq = (r == 0) ? sfq0 : sfq1;
            uint32_t doff = (uint32_t)(row * LDU + fq * 4) * 4;
            int grow = rowBase + row;
            size_t ab = (size_t)grow * KP + kp0 + fq * 4;
            int sz = (grow < M) ? 16 : 0;
            cpa16(sb + 0 * AR * 4 + doff, AH + ab, sz);
            cpa16(sb + 1 * AR * 4 + doff, AL + ab, sz);
            size_t bb = (size_t)(colBase + row) * KP + kp0 + fq * 4;
            cpa16(sb + 2 * AR * 4 + doff, WH + bb, 16);
            cpa16(sb + 3 * AR * 4 + doff, WL + bb, 16);
        }
        asm volatile("cp.async.commit_group;");
    };

    prefetch(0, 0);

    for (int t = 0; t < NT; t++) {
        int s = t & 1;
        if (t + 1 < NT) {
            prefetch(t + 1, (t + 1) & 1);
            asm volatile("cp.async.wait_group 1;");
        } else {
            asm volatile("cp.async.wait_group 0;");
        }
        __syncthreads();

        uint32_t aH_b = sbase + (uint32_t)(s * STG + 0 * AR) * 4;
        uint32_t aL_b = sbase + (uint32_t)(s * STG + 1 * AR) * 4;
        uint32_t bH_b = sbase + (uint32_t)(s * STG + 2 * AR) * 4;
        uint32_t bL_b = sbase + (uint32_t)(s * STG + 3 * AR) * 4;

        #pragma unroll
        for (int ks = 0; ks < 2; ks++) {
            int base = ks * 8;
            uint32_t bh[4][2], bl[4][2];
            #pragma unroll
            for (int nfp = 0; nfp < 2; nfp++) {
                uint32_t off = ((uint32_t)(bRow + nfp * 16) * LDU + base + bCol) * 4;
                uint32_t rh[4], rl[4];
                ldmx4(rh, bH_b + off);
                ldmx4(rl, bL_b + off);
                bh[2 * nfp][0] = rh[0]; bh[2 * nfp][1] = rh[1];
                bh[2 * nfp + 1][0] = rh[2]; bh[2 * nfp + 1][1] = rh[3];
                bl[2 * nfp][0] = rl[0]; bl[2 * nfp][1] = rl[1];
                bl[2 * nfp + 1][0] = rl[2]; bl[2 * nfp + 1][1] = rl[3];
            }
            #pragma unroll
            for (int mf = 0; mf < 4; mf++) {
                uint32_t off = ((uint32_t)(aRow + mf * 16) * LDU + base + aCol) * 4;
                uint32_t ah[4], al[4];
                ldmx4(ah, aH_b + off);
                ldmx4(al, aL_b + off);
                #pragma unroll
                for (int nf = 0; nf < 4; nf++) {
                    mma_bf16(d[mf][nf], ah, bh[nf]);   // hi*hi
                    mma_bf16(d[mf][nf], ah, bl[nf]);   // hi*lo
                    mma_bf16(d[mf][nf], al, bh[nf]);   // lo*hi
                }
            }
        }
        __syncthreads();
    }

    // --- epilogue ---
    #pragma unroll
    for (int nf = 0; nf < 4; nf++) {
        int col = colBase + wn * 32 + nf * 8 + tig * 2;
        int lcol = wn * 32 + nf * 8 + tig * 2;
        float b0 = __ldg(&bias[col]);
        float b1 = __ldg(&bias[col + 1]);
        float s0 = 0.f, q0 = 0.f, s1 = 0.f, q1 = 0.f;
        #pragma unroll
        for (int mf = 0; mf < 4; mf++) {
            int row = rowBase + wm * 64 + mf * 16 + gid;
            if (row < M) {
                float v0 = d[mf][nf][0] + b0;
                float v1 = d[mf][nf][1] + b1;
                if (SEL == 0) {
                    v0 = fmaxf(v0, 0.f); v1 = fmaxf(v1, 0.f);
                    uint32_t hi, lo;
                    split_pair(v0, v1, hi, lo);
                    size_t p = (size_t)row * (NC / 2) + (col >> 1);
                    g_hmidH[p] = hi; g_hmidL[p] = lo;
                } else {
                    g_h2[(size_t)row * NC + col] = v0;
                    g_h2[(size_t)row * NC + col + 1] = v1;
                    s0 += v0; q0 += v0 * v0; s1 += v1; q1 += v1 * v1;
                }
            }
            if (row + 8 < M) {
                float v2 = d[mf][nf][2] + b0;
                float v3 = d[mf][nf][3] + b1;
                if (SEL == 0) {
                    v2 = fmaxf(v2, 0.f); v3 = fmaxf(v3, 0.f);
                    uint32_t hi, lo;
                    split_pair(v2, v3, hi, lo);
                    size_t p = (size_t)(row + 8) * (NC / 2) + (col >> 1);
                    g_hmidH[p] = hi; g_hmidL[p] = lo;
                } else {
                    g_h2[(size_t)(row + 8) * NC + col] = v2;
                    g_h2[(size_t)(row + 8) * NC + col + 1] = v3;
                    s0 += v2; q0 += v2 * v2; s1 += v3; q1 += v3 * v3;
                }
            }
        }
        if (SEL == 1) {
            atomicAdd(&sSum[lcol], s0); atomicAdd(&sSq[lcol], q0);
            atomicAdd(&sSum[lcol + 1], s1); atomicAdd(&sSq[lcol + 1], q1);
        }
    }
    if (SEL == 1) {
        __syncthreads();
        if (tid < BN) {
            atomicAdd(&g_stats[colBase + tid], sSum[tid]);
            atomicAdd(&g_stats[EMB + colBase + tid], sSq[tid]);
        }
    }
}

// ----------------------------------------------------------------------------
__global__ void bn_finalize_kernel(const float* __restrict__ bn_w, const float* __restrict__ bn_b) {
    int c = threadIdx.x;
    if (c >= EMB) return;
    float invN = 1.0f / (float)NN_NODES;
    float mean = g_stats[c] * invN;
    float var = g_stats[EMB + c] * invN - mean * mean;
    float sc = bn_w[c] * rsqrtf(var + BN_EPS);
    g_scale[c] = sc;
    g_shift[c] = bn_b[c] - mean * sc;
}

// ----------------------------------------------------------------------------
// Final output only: out = h2 * scale + shift (no relu on last layer).
// ----------------------------------------------------------------------------
__global__ void bn_apply_kernel(float* __restrict__ out_ext) {
    int t = blockIdx.x * blockDim.x + threadIdx.x;
    if (t >= NN_NODES * (EMB / 4)) return;
    int q = t & 63;
    float4 v = reinterpret_cast<const float4*>(g_h2)[t];
    float4 sc = reinterpret_cast<const float4*>(g_scale)[q];
    float4 sh = reinterpret_cast<const float4*>(g_shift)[q];
    v.x = v.x * sc.x + sh.x;
    v.y = v.y * sc.y + sh.y;
    v.z = v.z * sc.z + sh.z;
    v.w = v.w * sc.w + sh.w;
    reinterpret_cast<float4*>(out_ext)[t] = v;
}

// ----------------------------------------------------------------------------
extern "C" void kernel_launch(void* const* d_in, const int* in_sizes, int n_in,
                              void* d_out, int out_size) {
    const int*   x_atom    = (const int*)d_in[0];
    const int*   x_chir    = (const int*)d_in[1];
    const int*   edge_idx  = (const int*)d_in[2];    // [2,E]
    const int*   edge_bond = (const int*)d_in[3];
    const int*   edge_dir  = (const int*)d_in[4];
    const float* atom_emb  = (const float*)d_in[5];  // [120,256]
    const float* chir_emb  = (const float*)d_in[6];  // [3,256]
    const float* bond_embs = (const float*)d_in[7];  // [5,6,256]
    const float* dir_embs  = (const float*)d_in[8];  // [5,3,256]
    const float* W1s       = (const float*)d_in[9];  // [5,512,256]
    const float* b1s       = (const float*)d_in[10]; // [5,512]
    const float* W2s       = (const float*)d_in[11]; // [5,256,512]
    const float* b2s       = (const float*)d_in[12]; // [5,256]
    const float* bn_w      = (const float*)d_in[13]; // [5,256]
    const float* bn_b      = (const float*)d_in[14]; // [5,256]
    float* out = (float*)d_out;

    const int* src = edge_idx;
    const int* dst = edge_idx + EE_EDGES;

    const int SMEM_GEMM = 2 * 4 * 128 * 20 * 4;   // 81920 B
    cudaFuncSetAttribute(gemm_tc_kernel<0>, cudaFuncAttributeMaxDynamicSharedMemorySize, SMEM_GEMM);
    cudaFuncSetAttribute(gemm_tc_kernel<1>, cudaFuncAttributeMaxDynamicSharedMemorySize, SMEM_GEMM);

    // --- preprocessing ---
    zero_scratch_kernel<<<512, 256>>>();
    hist_kernel<<<cdiv(EE_EDGES, 256), 256>>>(src, dst, edge_bond, edge_dir);
    scan_kernel<<<1, 1024>>>();
    fill_kernel<<<cdiv(EE_EDGES, 256), 256>>>(src, dst);
    init_h_kernel<<<cdiv(NN_NODES * (EMB / 4), 256), 256>>>(x_atom, x_chir, atom_emb, chir_emb);
    split_w_kernel<<<cdiv(2 * NUM_LAYER * 512 * 128, 256), 256>>>(W1s, W2s);

    dim3 g1(cdiv(NN_NODES, 128), 2 * EMB / 128);  // 782 x 4
    dim3 g2(cdiv(NN_NODES, 128), EMB / 128);      // 782 x 2
    const int aggBlocks = 592;                    // grid-stride: 4736 warps
    int applyBlocks = cdiv(NN_NODES * (EMB / 4), 256);

    for (int l = 0; l < NUM_LAYER; l++) {
        const float* BE = bond_embs + (size_t)l * 6 * EMB;
        const float* DE = dir_embs + (size_t)l * 3 * EMB;
        const float* B1 = b1s + (size_t)l * 2 * EMB;
        const float* B2 = b2s + (size_t)l * EMB;

        if (l == 0) agg_kernel<0><<<aggBlocks, 256>>>(BE, DE);
        else        agg_kernel<1><<<aggBlocks, 256>>>(BE, DE);
        gemm_tc_kernel<0><<<g1, 256, SMEM_GEMM>>>(B1, l);   // hmid = relu(agg@W1^T+b1)
        zero_stats_kernel<<<1, 512>>>();
        gemm_tc_kernel<1><<<g2, 256, SMEM_GEMM>>>(B2, l);   // h2 = hmid@W2^T+b2 (+stats)
        bn_finalize_kernel<<<1, 256>>>(bn_w + l * EMB, bn_b + l * EMB);
    }
    bn_apply_kernel<<<applyBlocks, 256>>>(out);             // final: affine only
}

// round 13
// speedup vs baseline: 2.5174x; 1.0592x over previous
#include <cuda_runtime.h>
#include <cuda_bf16.h>
#include <cstdint>

#define NN_NODES 100000
#define EE_EDGES 300000
#define EMB 256
#define NUM_LAYER 5
#define BN_EPS 1e-5f

static inline int cdiv(int a, int b) { return (a + b - 1) / b; }

// ----------------------------------------------------------------------------
// Device scratch. Symbols only referenced from device code.
// Split-bf16: pair (k,k+1) packed bf16x2 in u32; value = hi + lo.
// ----------------------------------------------------------------------------
__device__ float    g_h   [(size_t)NN_NODES * EMB];          // layer-0 node features
__device__ float    g_h2  [(size_t)NN_NODES * EMB];          // MLP out pre-BN (fp32)
__device__ uint32_t g_aggH[(size_t)NN_NODES * (EMB / 2)];
__device__ uint32_t g_aggL[(size_t)NN_NODES * (EMB / 2)];
__device__ uint32_t g_hmidH[(size_t)NN_NODES * EMB];
__device__ uint32_t g_hmidL[(size_t)NN_NODES * EMB];
__device__ uint32_t g_w1H[NUM_LAYER * 512 * 128];
__device__ uint32_t g_w1L[NUM_LAYER * 512 * 128];
__device__ uint32_t g_w2H[NUM_LAYER * 256 * 256];
__device__ uint32_t g_w2L[NUM_LAYER * 256 * 256];

__device__ int   g_indeg[NN_NODES];
__device__ int   g_off  [NN_NODES];
__device__ int   g_ctr  [NN_NODES];
__device__ int   g_adj  [EE_EDGES];
__device__ int   g_cntb [NN_NODES * 4];
__device__ int   g_cntd [NN_NODES * 4];
__device__ float g_stats[2 * EMB];
__device__ float g_scale[EMB];
__device__ float g_shift[EMB];

// ----------------------------------------------------------------------------
__device__ __forceinline__ uint32_t pack2bf(float a, float b) {
    __nv_bfloat162 t = __floats2bfloat162_rn(a, b);
    return *reinterpret_cast<uint32_t*>(&t);
}

__device__ __forceinline__ void split_pair(float a, float b, uint32_t& hi, uint32_t& lo) {
    __nv_bfloat16 ha = __float2bfloat16_rn(a);
    __nv_bfloat16 hb = __float2bfloat16_rn(b);
    __nv_bfloat162 h; h.x = ha; h.y = hb;
    hi = *reinterpret_cast<uint32_t*>(&h);
    lo = pack2bf(a - __bfloat162float(ha), b - __bfloat162float(hb));
}

// ----------------------------------------------------------------------------
__global__ void zero_scratch_kernel() {
    int t = blockIdx.x * blockDim.x + threadIdx.x;
    int stride = gridDim.x * blockDim.x;
    for (int i = t; i < NN_NODES; i += stride) { g_indeg[i] = 0; g_ctr[i] = 0; }
    for (int i = t; i < NN_NODES * 4; i += stride) { g_cntb[i] = 0; g_cntd[i] = 0; }
}

// ----------------------------------------------------------------------------
__global__ void split_w_kernel(const float* __restrict__ W1s, const float* __restrict__ W2s) {
    constexpr int NP = NUM_LAYER * 512 * 128;
    int t = blockIdx.x * blockDim.x + threadIdx.x;
    if (t < NP) {
        uint32_t hi, lo;
        split_pair(W1s[2 * t], W1s[2 * t + 1], hi, lo);
        g_w1H[t] = hi; g_w1L[t] = lo;
    } else if (t < 2 * NP) {
        int u = t - NP;
        uint32_t hi, lo;
        split_pair(W2s[2 * u], W2s[2 * u + 1], hi, lo);
        g_w2H[u] = hi; g_w2L[u] = lo;
    }
}

// ----------------------------------------------------------------------------
__global__ void hist_kernel(const int* __restrict__ src, const int* __restrict__ dst,
                            const int* __restrict__ bond, const int* __restrict__ dir) {
    int e = blockIdx.x * blockDim.x + threadIdx.x;
    if (e >= EE_EDGES) return;
    int d = dst[e];
    atomicAdd(&g_indeg[d], 1);
    atomicAdd(&g_cntb[d * 4 + bond[e]], 1);
    atomicAdd(&g_cntd[d * 4 + dir[e]], 1);
}

// ----------------------------------------------------------------------------
__global__ void scan_kernel() {
    __shared__ int s[1024];
    __shared__ int carry;
    int t = threadIdx.x;
    if (t == 0) carry = 0;
    __syncthreads();
    for (int base = 0; base < NN_NODES; base += 1024) {
        int i = base + t;
        int v = (i < NN_NODES) ? g_indeg[i] : 0;
        s[t] = v;
        __syncthreads();
        #pragma unroll
        for (int off = 1; off < 1024; off <<= 1) {
            int x = (t >= off) ? s[t - off] : 0;
            __syncthreads();
            s[t] += x;
            __syncthreads();
        }
        int incl = s[t];
        int c = carry;
        if (i < NN_NODES) g_off[i] = c + incl - v;
        __syncthreads();
        if (t == 1023) carry = c + s[1023];
        __syncthreads();
    }
}

// ----------------------------------------------------------------------------
__global__ void fill_kernel(const int* __restrict__ src, const int* __restrict__ dst) {
    int e = blockIdx.x * blockDim.x + threadIdx.x;
    if (e >= EE_EDGES) return;
    int d = dst[e];
    int p = atomicAdd(&g_ctr[d], 1);
    g_adj[g_off[d] + p] = src[e];
}

// ----------------------------------------------------------------------------
__global__ void init_h_kernel(const int* __restrict__ x_atom, const int* __restrict__ x_chir,
                              const float* __restrict__ atom_emb, const float* __restrict__ chir_emb) {
    int t = blockIdx.x * blockDim.x + threadIdx.x;
    if (t >= NN_NODES * (EMB / 4)) return;
    int row = t >> 6;
    int q = t & 63;
    int a = x_atom[row];
    int c = x_chir[row];
    float4 va = reinterpret_cast<const float4*>(atom_emb)[a * 64 + q];
    float4 vc = reinterpret_cast<const float4*>(chir_emb)[c * 64 + q];
    float4 o;
    o.x = va.x + vc.x; o.y = va.y + vc.y; o.z = va.z + vc.z; o.w = va.w + vc.w;
    reinterpret_cast<float4*>(g_h)[t] = o;
}

// ----------------------------------------------------------------------------
// Aggregation: one warp per node via grid-stride; 8x8 per-lane embedding slice
// in registers; BN+ReLU fused on the input side (MODE=1). Edge loop unrolled x4.
// ----------------------------------------------------------------------------
template <int MODE>
__global__ void __launch_bounds__(256)
agg_kernel(const float* __restrict__ bondE,   // 6x256 (rows 0..4 used)
           const float* __restrict__ dirE) {  // 3x256
    int tid = threadIdx.x;
    int lane = tid & 31;
    int warpG = blockIdx.x * 8 + (tid >> 5);
    int nWarps = gridDim.x * 8;
    int c0 = lane * 8;

    float base[8], tB0[8], tB1[8], tB2[8], tB3[8], tD0[8], tD1[8], tD2[8];
    #pragma unroll
    for (int c = 0; c < 8; c++) {
        int cc = c0 + c;
        tB0[c] = __ldg(&bondE[0 * EMB + cc]);
        tB1[c] = __ldg(&bondE[1 * EMB + cc]);
        tB2[c] = __ldg(&bondE[2 * EMB + cc]);
        tB3[c] = __ldg(&bondE[3 * EMB + cc]);
        tD0[c] = __ldg(&dirE[0 * EMB + cc]);
        tD1[c] = __ldg(&dirE[1 * EMB + cc]);
        tD2[c] = __ldg(&dirE[2 * EMB + cc]);
        base[c] = __ldg(&bondE[4 * EMB + cc]) + tD0[c];
    }

    float sc[8], sh[8];
    if (MODE == 1) {
        #pragma unroll
        for (int c = 0; c < 8; c++) {
            sc[c] = __ldg(&g_scale[c0 + c]);
            sh[c] = __ldg(&g_shift[c0 + c]);
        }
    }

    const float* __restrict__ H = (MODE == 0) ? g_h : g_h2;

    for (int node = warpG; node < NN_NODES; node += nWarps) {
        int4 cb = *reinterpret_cast<const int4*>(&g_cntb[node * 4]);
        int4 cd = *reinterpret_cast<const int4*>(&g_cntd[node * 4]);
        float fb0 = (float)cb.x, fb1 = (float)cb.y, fb2 = (float)cb.z, fb3 = (float)cb.w;
        float fd0 = (float)cd.x, fd1 = (float)cd.y, fd2 = (float)cd.z;

        float acc[8];
        #pragma unroll
        for (int c = 0; c < 8; c++) {
            float v = base[c];
            v = fmaf(fb0, tB0[c], v);
            v = fmaf(fb1, tB1[c], v);
            v = fmaf(fb2, tB2[c], v);
            v = fmaf(fb3, tB3[c], v);
            v = fmaf(fd0, tD0[c], v);
            v = fmaf(fd1, tD1[c], v);
            v = fmaf(fd2, tD2[c], v);
            acc[c] = v;
        }

        {   // self row
            const float4* hrow = reinterpret_cast<const float4*>(H + (size_t)node * EMB + c0);
            float4 a0 = hrow[0], a1 = hrow[1];
            float raw[8] = {a0.x, a0.y, a0.z, a0.w, a1.x, a1.y, a1.z, a1.w};
            #pragma unroll
            for (int c = 0; c < 8; c++)
                acc[c] += (MODE == 0) ? raw[c] : fmaxf(fmaf(raw[c], sc[c], sh[c]), 0.f);
        }

        int s = g_off[node];
        int eEnd = s + g_indeg[node];
        int e = s;
        for (; e + 4 <= eEnd; e += 4) {
            int j0 = __ldg(&g_adj[e]);
            int j1 = __ldg(&g_adj[e + 1]);
            int j2 = __ldg(&g_adj[e + 2]);
            int j3 = __ldg(&g_adj[e + 3]);
            const float4* h0 = reinterpret_cast<const float4*>(H + (size_t)j0 * EMB + c0);
            const float4* h1 = reinterpret_cast<const float4*>(H + (size_t)j1 * EMB + c0);
            const float4* h2 = reinterpret_cast<const float4*>(H + (size_t)j2 * EMB + c0);
            const float4* h3 = reinterpret_cast<const float4*>(H + (size_t)j3 * EMB + c0);
            float4 a0 = h0[0], a1 = h0[1], b0 = h1[0], b1 = h1[1];
            float4 e0 = h2[0], e1 = h2[1], f0 = h3[0], f1 = h3[1];
            float r0[8] = {a0.x, a0.y, a0.z, a0.w, a1.x, a1.y, a1.z, a1.w};
            float r1[8] = {b0.x, b0.y, b0.z, b0.w, b1.x, b1.y, b1.z, b1.w};
            float r2[8] = {e0.x, e0.y, e0.z, e0.w, e1.x, e1.y, e1.z, e1.w};
            float r3[8] = {f0.x, f0.y, f0.z, f0.w, f1.x, f1.y, f1.z, f1.w};
            if (MODE == 0) {
                #pragma unroll
                for (int c = 0; c < 8; c++) acc[c] += (r0[c] + r1[c]) + (r2[c] + r3[c]);
            } else {
                #pragma unroll
                for (int c = 0; c < 8; c++) {
                    acc[c] += fmaxf(fmaf(r0[c], sc[c], sh[c]), 0.f);
                    acc[c] += fmaxf(fmaf(r1[c], sc[c], sh[c]), 0.f);
                    acc[c] += fmaxf(fmaf(r2[c], sc[c], sh[c]), 0.f);
                    acc[c] += fmaxf(fmaf(r3[c], sc[c], sh[c]), 0.f);
                }
            }
        }
        for (; e < eEnd; e++) {
            int j = __ldg(&g_adj[e]);
            const float4* hj = reinterpret_cast<const float4*>(H + (size_t)j * EMB + c0);
            float4 b0 = hj[0], b1 = hj[1];
            float raw[8] = {b0.x, b0.y, b0.z, b0.w, b1.x, b1.y, b1.z, b1.w};
            #pragma unroll
            for (int c = 0; c < 8; c++)
                acc[c] += (MODE == 0) ? raw[c] : fmaxf(fmaf(raw[c], sc[c], sh[c]), 0.f);
        }

        uint4 hv, lv;
        split_pair(acc[0], acc[1], hv.x, lv.x);
        split_pair(acc[2], acc[3], hv.y, lv.y);
        split_pair(acc[4], acc[5], hv.z, lv.z);
        split_pair(acc[6], acc[7], hv.w, lv.w);
        size_t obase = (size_t)node * (EMB / 2) + lane * 4;
        *reinterpret_cast<uint4*>(&g_aggH[obase]) = hv;
        *reinterpret_cast<uint4*>(&g_aggL[obase]) = lv;
    }
}

// ----------------------------------------------------------------------------
// Split-BF16 tensor-core GEMM: cp.async double-buffered (1 sync/tile),
// ldmatrix frags, 2 CTAs/SM via launch_bounds reg cap.
//   D += Ahi*Bhi + Ahi*Blo + Alo*Bhi   (m16n8k16.bf16)
// Block 128x128, BK=32 elements (16 pairs), 8 warps (2x4).
//   SEL=0: A=g_agg (K=256) -> g_hmid split + ReLU (NC=512); also zeroes g_stats
//   SEL=1: A=g_hmid (K=512) -> g_h2 fp32 + BN stats (NC=256)
// ----------------------------------------------------------------------------
__device__ __forceinline__ void mma_bf16(float d[4], const uint32_t a[4], const uint32_t b[2]) {
    asm volatile(
        "mma.sync.aligned.m16n8k16.row.col.f32.bf16.bf16.f32 "
        "{%0,%1,%2,%3}, {%4,%5,%6,%7}, {%8,%9}, {%0,%1,%2,%3};"
        : "+f"(d[0]), "+f"(d[1]), "+f"(d[2]), "+f"(d[3])
        : "r"(a[0]), "r"(a[1]), "r"(a[2]), "r"(a[3]), "r"(b[0]), "r"(b[1]));
}

__device__ __forceinline__ void ldmx4(uint32_t* r, uint32_t addr) {
    asm volatile("ldmatrix.sync.aligned.m8n8.x4.shared.b16 {%0,%1,%2,%3}, [%4];"
                 : "=r"(r[0]), "=r"(r[1]), "=r"(r[2]), "=r"(r[3]) : "r"(addr));
}

__device__ __forceinline__ void cpa16(uint32_t dst, const void* src, int szbytes) {
    asm volatile("cp.async.cg.shared.global [%0], [%1], 16, %2;"
                 :: "r"(dst), "l"(src), "r"(szbytes));
}

template <int SEL>
__global__ void __launch_bounds__(256, 2)
gemm_tc_kernel(const float* __restrict__ bias, int layer) {
    constexpr int M = NN_NODES;
    constexpr int K = (SEL == 0) ? EMB : 2 * EMB;
    constexpr int NC = (SEL == 0) ? 2 * EMB : EMB;
    constexpr int KP = K / 2;
    const uint32_t* __restrict__ AH = (SEL == 0) ? g_aggH : g_hmidH;
    const uint32_t* __restrict__ AL = (SEL == 0) ? g_aggL : g_hmidL;
    const uint32_t* __restrict__ WH = ((SEL == 0) ? g_w1H : g_w2H) + (size_t)layer * NC * KP;
    const uint32_t* __restrict__ WL = ((SEL == 0) ? g_w1L : g_w2L) + (size_t)layer * NC * KP;

    constexpr int BM = 128, BN = 128;
    constexpr int BKP = 16;              // pairs per K-tile
    constexpr int LDU = BKP + 4;         // stride 20 u32: ldmatrix conflict-free
    constexpr int AR = BM * LDU;         // 2560 u32 per array
    constexpr int STG = 4 * AR;          // u32 per stage
    constexpr int NT = KP / BKP;         // K tiles

    extern __shared__ uint32_t dsm[];
    __shared__ float sSum[BN];
    __shared__ float sSq[BN];
    uint32_t sbase = (uint32_t)__cvta_generic_to_shared(dsm);

    int tid = threadIdx.x;
    int wid = tid >> 5, lane = tid & 31;
    int wm = wid & 1;
    int wn = wid >> 1;
    int rowBase = blockIdx.x * BM;
    int colBase = blockIdx.y * BN;

    if (SEL == 1 && tid < BN) { sSum[tid] = 0.f; sSq[tid] = 0.f; }
    // GEMM1 zeroes the stats buffer for the following GEMM2 (stream-ordered)
    if (SEL == 0 && blockIdx.x == 0 && blockIdx.y == 0 && tid < 256) {
        g_stats[tid] = 0.f;
        g_stats[256 + tid] = 0.f;
    }

    float d[4][4][4];
    #pragma unroll
    for (int i = 0; i < 4; i++)
        #pragma unroll
        for (int j = 0; j < 4; j++)
            #pragma unroll
            for (int r = 0; r < 4; r++) d[i][j][r] = 0.0f;

    int gid = lane >> 2;
    int tig = lane & 3;

    int srow0 = tid >> 2;
    int sfq0 = tid & 3;
    int srow1 = (tid + 256) >> 2;

    int aRow = wm * 64 + (lane & 15);
    int aCol = (lane >> 4) * 4;
    int bRow = wn * 32 + (lane & 7) + ((lane >> 4) << 3);
    int bCol = ((lane >> 3) & 1) * 4;

    auto prefetch = [&](int t, int s) {
        int kp0 = t * BKP;
        uint32_t sb = sbase + (uint32_t)(s * STG) * 4;
        #pragma unroll
        for (int r = 0; r < 2; r++) {
            int row = (r == 0) ? srow0 : srow1;
            uint32_t doff = (uint32_t)(row * LDU + sfq0 * 4) * 4;
            int grow = rowBase + row;
            size_t ab = (size_t)grow * KP + kp0 + sfq0 * 4;
            int sz = (grow < M) ? 16 : 0;
            cpa16(sb + 0 * AR * 4 + doff, AH + ab, sz);
            cpa16(sb + 1 * AR * 4 + doff, AL + ab, sz);
            size_t bb = (size_t)(colBase + row) * KP + kp0 + sfq0 * 4;
            cpa16(sb + 2 * AR * 4 + doff, WH + bb, 16);
            cpa16(sb + 3 * AR * 4 + doff, WL + bb, 16);
        }
        asm volatile("cp.async.commit_group;");
    };

    prefetch(0, 0);

    for (int t = 0; t < NT; t++) {
        int s = t & 1;
        // only prefetch(t) is in flight here (t+1 not yet issued)
        asm volatile("cp.async.wait_group 0;");
        __syncthreads();
        if (t + 1 < NT) prefetch(t + 1, 1 - s);

        uint32_t aH_b = sbase + (uint32_t)(s * STG + 0 * AR) * 4;
        uint32_t aL_b = sbase + (uint32_t)(s * STG + 1 * AR) * 4;
        uint32_t bH_b = sbase + (uint32_t)(s * STG + 2 * AR) * 4;
        uint32_t bL_b = sbase + (uint32_t)(s * STG + 3 * AR) * 4;

        #pragma unroll
        for (int ks = 0; ks < 2; ks++) {
            int base = ks * 8;
            uint32_t bh[4][2], bl[4][2];
            #pragma unroll
            for (int nfp = 0; nfp < 2; nfp++) {
                uint32_t off = ((uint32_t)(bRow + nfp * 16) * LDU + base + bCol) * 4;
                uint32_t rh[4], rl[4];
                ldmx4(rh, bH_b + off);
                ldmx4(rl, bL_b + off);
                bh[2 * nfp][0] = rh[0]; bh[2 * nfp][1] = rh[1];
                bh[2 * nfp + 1][0] = rh[2]; bh[2 * nfp + 1][1] = rh[3];
                bl[2 * nfp][0] = rl[0]; bl[2 * nfp][1] = rl[1];
                bl[2 * nfp + 1][0] = rl[2]; bl[2 * nfp + 1][1] = rl[3];
            }
            #pragma unroll
            for (int mf = 0; mf < 4; mf++) {
                uint32_t off = ((uint32_t)(aRow + mf * 16) * LDU + base + aCol) * 4;
                uint32_t ah[4], al[4];
                ldmx4(ah, aH_b + off);
                ldmx4(al, aL_b + off);
                #pragma unroll
                for (int nf = 0; nf < 4; nf++) {
                    mma_bf16(d[mf][nf], ah, bh[nf]);   // hi*hi
                    mma_bf16(d[mf][nf], ah, bl[nf]);   // hi*lo
                    mma_bf16(d[mf][nf], al, bh[nf]);   // lo*hi
                }
            }
        }
        __syncthreads();   // compute done before next iter's buffer overwrite
    }

    // --- epilogue ---
    #pragma unroll
    for (int nf = 0; nf < 4; nf++) {
        int col = colBase + wn * 32 + nf * 8 + tig * 2;
        int lcol = wn * 32 + nf * 8 + tig * 2;
        float b0 = __ldg(&bias[col]);
        float b1 = __ldg(&bias[col + 1]);
        float s0 = 0.f, q0 = 0.f, s1 = 0.f, q1 = 0.f;
        #pragma unroll
        for (int mf = 0; mf < 4; mf++) {
            int row = rowBase + wm * 64 + mf * 16 + gid;
            if (row < M) {
                float v0 = d[mf][nf][0] + b0;
                float v1 = d[mf][nf][1] + b1;
                if (SEL == 0) {
                    v0 = fmaxf(v0, 0.f); v1 = fmaxf(v1, 0.f);
                    uint32_t hi, lo;
                    split_pair(v0, v1, hi, lo);
                    size_t p = (size_t)row * (NC / 2) + (col >> 1);
                    g_hmidH[p] = hi; g_hmidL[p] = lo;
                } else {
                    g_h2[(size_t)row * NC + col] = v0;
                    g_h2[(size_t)row * NC + col + 1] = v1;
                    s0 += v0; q0 += v0 * v0; s1 += v1; q1 += v1 * v1;
                }
            }
            if (row + 8 < M) {
                float v2 = d[mf][nf][2] + b0;
                float v3 = d[mf][nf][3] + b1;
                if (SEL == 0) {
                    v2 = fmaxf(v2, 0.f); v3 = fmaxf(v3, 0.f);
                    uint32_t hi, lo;
                    split_pair(v2, v3, hi, lo);
                    size_t p = (size_t)(row + 8) * (NC / 2) + (col >> 1);
                    g_hmidH[p] = hi; g_hmidL[p] = lo;
                } else {
                    g_h2[(size_t)(row + 8) * NC + col] = v2;
                    g_h2[(size_t)(row + 8) * NC + col + 1] = v3;
                    s0 += v2; q0 += v2 * v2; s1 += v3; q1 += v3 * v3;
                }
            }
        }
        if (SEL == 1) {
            atomicAdd(&sSum[lcol], s0); atomicAdd(&sSq[lcol], q0);
            atomicAdd(&sSum[lcol + 1], s1); atomicAdd(&sSq[lcol + 1], q1);
        }
    }
    if (SEL == 1) {
        __syncthreads();
        if (tid < BN) {
            atomicAdd(&g_stats[colBase + tid], sSum[tid]);
            atomicAdd(&g_stats[EMB + colBase + tid], sSq[tid]);
        }
    }
}

// ----------------------------------------------------------------------------
__global__ void bn_finalize_kernel(const float* __restrict__ bn_w, const float* __restrict__ bn_b) {
    int c = threadIdx.x;
    if (c >= EMB) return;
    float invN = 1.0f / (float)NN_NODES;
    float mean = g_stats[c] * invN;
    float var = g_stats[EMB + c] * invN - mean * mean;
    float sc = bn_w[c] * rsqrtf(var + BN_EPS);
    g_scale[c] = sc;
    g_shift[c] = bn_b[c] - mean * sc;
}

// ----------------------------------------------------------------------------
// Final output only: out = h2 * scale + shift (no relu on last layer).
// ----------------------------------------------------------------------------
__global__ void bn_apply_kernel(float* __restrict__ out_ext) {
    int t = blockIdx.x * blockDim.x + threadIdx.x;
    if (t >= NN_NODES * (EMB / 4)) return;
    int q = t & 63;
    float4 v = reinterpret_cast<const float4*>(g_h2)[t];
    float4 sc = reinterpret_cast<const float4*>(g_scale)[q];
    float4 sh = reinterpret_cast<const float4*>(g_shift)[q];
    v.x = v.x * sc.x + sh.x;
    v.y = v.y * sc.y + sh.y;
    v.z = v.z * sc.z + sh.z;
    v.w = v.w * sc.w + sh.w;
    reinterpret_cast<float4*>(out_ext)[t] = v;
}

// ----------------------------------------------------------------------------
extern "C" void kernel_launch(void* const* d_in, const int* in_sizes, int n_in,
                              void* d_out, int out_size) {
    const int*   x_atom    = (const int*)d_in[0];
    const int*   x_chir    = (const int*)d_in[1];
    const int*   edge_idx  = (const int*)d_in[2];    // [2,E]
    const int*   edge_bond = (const int*)d_in[3];
    const int*   edge_dir  = (const int*)d_in[4];
    const float* atom_emb  = (const float*)d_in[5];  // [120,256]
    const float* chir_emb  = (const float*)d_in[6];  // [3,256]
    const float* bond_embs = (const float*)d_in[7];  // [5,6,256]
    const float* dir_embs  = (const float*)d_in[8];  // [5,3,256]
    const float* W1s       = (const float*)d_in[9];  // [5,512,256]
    const float* b1s       = (const float*)d_in[10]; // [5,512]
    const float* W2s       = (const float*)d_in[11]; // [5,256,512]
    const float* b2s       = (const float*)d_in[12]; // [5,256]
    const float* bn_w      = (const float*)d_in[13]; // [5,256]
    const float* bn_b      = (const float*)d_in[14]; // [5,256]
    float* out = (float*)d_out;

    const int* src = edge_idx;
    const int* dst = edge_idx + EE_EDGES;

    const int SMEM_GEMM = 2 * 4 * 128 * 20 * 4;   // 81920 B
    cudaFuncSetAttribute(gemm_tc_kernel<0>, cudaFuncAttributeMaxDynamicSharedMemorySize, SMEM_GEMM);
    cudaFuncSetAttribute(gemm_tc_kernel<1>, cudaFuncAttributeMaxDynamicSharedMemorySize, SMEM_GEMM);

    // --- preprocessing ---
    zero_scratch_kernel<<<512, 256>>>();
    hist_kernel<<<cdiv(EE_EDGES, 256), 256>>>(src, dst, edge_bond, edge_dir);
    scan_kernel<<<1, 1024>>>();
    fill_kernel<<<cdiv(EE_EDGES, 256), 256>>>(src, dst);
    init_h_kernel<<<cdiv(NN_NODES * (EMB / 4), 256), 256>>>(x_atom, x_chir, atom_emb, chir_emb);
    split_w_kernel<<<cdiv(2 * NUM_LAYER * 512 * 128, 256), 256>>>(W1s, W2s);

    dim3 g1(cdiv(NN_NODES, 128), 2 * EMB / 128);  // 782 x 4
    dim3 g2(cdiv(NN_NODES, 128), EMB / 128);      // 782 x 2
    const int aggBlocks = 592;                    // grid-stride: 4736 warps
    int applyBlocks = cdiv(NN_NODES * (EMB / 4), 256);

    for (int l = 0; l < NUM_LAYER; l++) {
        const float* BE = bond_embs + (size_t)l * 6 * EMB;
        const float* DE = dir_embs + (size_t)l * 3 * EMB;
        const float* B1 = b1s + (size_t)l * 2 * EMB;
        const float* B2 = b2s + (size_t)l * EMB;

        if (l == 0) agg_kernel<0><<<aggBlocks, 256>>>(BE, DE);
        else        agg_kernel<1><<<aggBlocks, 256>>>(BE, DE);
        gemm_tc_kernel<0><<<g1, 256, SMEM_GEMM>>>(B1, l);   // hmid = relu(agg@W1^T+b1), zeroes stats
        gemm_tc_kernel<1><<<g2, 256, SMEM_GEMM>>>(B2, l);   // h2 = hmid@W2^T+b2 (+stats)
        bn_finalize_kernel<<<1, 256>>>(bn_w + l * EMB, bn_b + l * EMB);
    }
    bn_apply_kernel<<<applyBlocks, 256>>>(out);             // final: affine only
}

// round 14
// speedup vs baseline: 2.6423x; 1.0496x over previous
#include <cuda_runtime.h>
#include <cuda_bf16.h>
#include <cstdint>

#define NN_NODES 100000
#define EE_EDGES 300000
#define EMB 256
#define NUM_LAYER 5
#define BN_EPS 1e-5f

static inline int cdiv(int a, int b) { return (a + b - 1) / b; }

// ----------------------------------------------------------------------------
// Device scratch. Symbols only referenced from device code.
// Split-bf16: pair (k,k+1) packed bf16x2 in u32; value = hi + lo.
// ----------------------------------------------------------------------------
__device__ float    g_h   [(size_t)NN_NODES * EMB];          // layer-0 node features
__device__ float    g_h2  [(size_t)NN_NODES * EMB];          // MLP out pre-BN (fp32)
__device__ uint32_t g_aggH[(size_t)NN_NODES * (EMB / 2)];
__device__ uint32_t g_aggL[(size_t)NN_NODES * (EMB / 2)];
__device__ uint32_t g_hmidH[(size_t)NN_NODES * EMB];
__device__ uint32_t g_hmidL[(size_t)NN_NODES * EMB];
__device__ uint32_t g_w1H[NUM_LAYER * 512 * 128];
__device__ uint32_t g_w1L[NUM_LAYER * 512 * 128];
__device__ uint32_t g_w2H[NUM_LAYER * 256 * 256];
__device__ uint32_t g_w2L[NUM_LAYER * 256 * 256];

__device__ int   g_indeg[NN_NODES];
__device__ int   g_off  [NN_NODES];
__device__ int   g_ctr  [NN_NODES];
__device__ int   g_adj  [EE_EDGES];
__device__ int   g_cntb [NN_NODES * 4];
__device__ int   g_cntd [NN_NODES * 4];
__device__ float g_stats[2 * EMB];
__device__ int   g_total;

// ----------------------------------------------------------------------------
__device__ __forceinline__ uint32_t pack2bf(float a, float b) {
    __nv_bfloat162 t = __floats2bfloat162_rn(a, b);
    return *reinterpret_cast<uint32_t*>(&t);
}

__device__ __forceinline__ void split_pair(float a, float b, uint32_t& hi, uint32_t& lo) {
    __nv_bfloat16 ha = __float2bfloat16_rn(a);
    __nv_bfloat16 hb = __float2bfloat16_rn(b);
    __nv_bfloat162 h; h.x = ha; h.y = hb;
    hi = *reinterpret_cast<uint32_t*>(&h);
    lo = pack2bf(a - __bfloat162float(ha), b - __bfloat162float(hb));
}

// ----------------------------------------------------------------------------
__global__ void zero_scratch_kernel() {
    int t = blockIdx.x * blockDim.x + threadIdx.x;
    int stride = gridDim.x * blockDim.x;
    if (t == 0) g_total = 0;
    for (int i = t; i < NN_NODES; i += stride) { g_indeg[i] = 0; g_ctr[i] = 0; }
    for (int i = t; i < NN_NODES * 4; i += stride) { g_cntb[i] = 0; g_cntd[i] = 0; }
}

// ----------------------------------------------------------------------------
__global__ void split_w_kernel(const float* __restrict__ W1s, const float* __restrict__ W2s) {
    constexpr int NP = NUM_LAYER * 512 * 128;
    int t = blockIdx.x * blockDim.x + threadIdx.x;
    if (t < NP) {
        uint32_t hi, lo;
        split_pair(W1s[2 * t], W1s[2 * t + 1], hi, lo);
        g_w1H[t] = hi; g_w1L[t] = lo;
    } else if (t < 2 * NP) {
        int u = t - NP;
        uint32_t hi, lo;
        split_pair(W2s[2 * u], W2s[2 * u + 1], hi, lo);
        g_w2H[u] = hi; g_w2L[u] = lo;
    }
}

// ----------------------------------------------------------------------------
__global__ void hist_kernel(const int* __restrict__ src, const int* __restrict__ dst,
                            const int* __restrict__ bond, const int* __restrict__ dir) {
    int e = blockIdx.x * blockDim.x + threadIdx.x;
    if (e >= EE_EDGES) return;
    int d = dst[e];
    atomicAdd(&g_indeg[d], 1);
    atomicAdd(&g_cntb[d * 4 + bond[e]], 1);
    atomicAdd(&g_cntd[d * 4 + dir[e]], 1);
}

// ----------------------------------------------------------------------------
// Offsets: block-level scan + one atomicAdd per block (order-free CSR --
// aggregation is an order-independent sum, so global slot order is irrelevant).
// ----------------------------------------------------------------------------
__global__ void offsets_kernel() {
    __shared__ int warpTot[8];
    __shared__ int blockBase;
    int tid = threadIdx.x, lane = tid & 31, w = tid >> 5;
    int i = blockIdx.x * 256 + tid;
    int v = (i < NN_NODES) ? g_indeg[i] : 0;
    int x = v;
    #pragma unroll
    for (int o = 1; o < 32; o <<= 1) {
        int y = __shfl_up_sync(0xFFFFFFFFu, x, o);
        if (lane >= o) x += y;
    }
    if (lane == 31) warpTot[w] = x;
    __syncthreads();
    if (tid == 0) {
        int s = 0;
        #pragma unroll
        for (int k = 0; k < 8; k++) { int t2 = warpTot[k]; warpTot[k] = s; s += t2; }
        blockBase = atomicAdd(&g_total, s);
    }
    __syncthreads();
    if (i < NN_NODES) g_off[i] = blockBase + warpTot[w] + x - v;
}

// ----------------------------------------------------------------------------
__global__ void fill_kernel(const int* __restrict__ src, const int* __restrict__ dst) {
    int e = blockIdx.x * blockDim.x + threadIdx.x;
    if (e >= EE_EDGES) return;
    int d = dst[e];
    int p = atomicAdd(&g_ctr[d], 1);
    g_adj[g_off[d] + p] = src[e];
}

// ----------------------------------------------------------------------------
__global__ void init_h_kernel(const int* __restrict__ x_atom, const int* __restrict__ x_chir,
                              const float* __restrict__ atom_emb, const float* __restrict__ chir_emb) {
    int t = blockIdx.x * blockDim.x + threadIdx.x;
    if (t >= NN_NODES * (EMB / 4)) return;
    int row = t >> 6;
    int q = t & 63;
    int a = x_atom[row];
    int c = x_chir[row];
    float4 va = reinterpret_cast<const float4*>(atom_emb)[a * 64 + q];
    float4 vc = reinterpret_cast<const float4*>(chir_emb)[c * 64 + q];
    float4 o;
    o.x = va.x + vc.x; o.y = va.y + vc.y; o.z = va.z + vc.z; o.w = va.w + vc.w;
    reinterpret_cast<float4*>(g_h)[t] = o;
}

// ----------------------------------------------------------------------------
// Aggregation: one warp per node via grid-stride; 8x8 per-lane embedding slice
// in registers; BN+ReLU fused on the input side (MODE=1), with scale/shift
// computed inline from g_stats + bn params (per-warp, 8 columns).
// ----------------------------------------------------------------------------
template <int MODE>
__global__ void __launch_bounds__(256)
agg_kernel(const float* __restrict__ bondE,   // 6x256 (rows 0..4 used)
           const float* __restrict__ dirE,    // 3x256
           const float* __restrict__ bnw,     // prev layer bn_w (MODE=1)
           const float* __restrict__ bnb) {   // prev layer bn_b (MODE=1)
    int tid = threadIdx.x;
    int lane = tid & 31;
    int warpG = blockIdx.x * 8 + (tid >> 5);
    int nWarps = gridDim.x * 8;
    int c0 = lane * 8;

    float base[8], tB0[8], tB1[8], tB2[8], tB3[8], tD0[8], tD1[8], tD2[8];
    #pragma unroll
    for (int c = 0; c < 8; c++) {
        int cc = c0 + c;
        tB0[c] = __ldg(&bondE[0 * EMB + cc]);
        tB1[c] = __ldg(&bondE[1 * EMB + cc]);
        tB2[c] = __ldg(&bondE[2 * EMB + cc]);
        tB3[c] = __ldg(&bondE[3 * EMB + cc]);
        tD0[c] = __ldg(&dirE[0 * EMB + cc]);
        tD1[c] = __ldg(&dirE[1 * EMB + cc]);
        tD2[c] = __ldg(&dirE[2 * EMB + cc]);
        base[c] = __ldg(&bondE[4 * EMB + cc]) + tD0[c];
    }

    float sc[8], sh[8];
    if (MODE == 1) {
        float invN = 1.0f / (float)NN_NODES;
        #pragma unroll
        for (int c = 0; c < 8; c++) {
            int cc = c0 + c;
            float mean = g_stats[cc] * invN;
            float var = g_stats[EMB + cc] * invN - mean * mean;
            float s = __ldg(&bnw[cc]) * rsqrtf(var + BN_EPS);
            sc[c] = s;
            sh[c] = __ldg(&bnb[cc]) - mean * s;
        }
    }

    const float* __restrict__ H = (MODE == 0) ? g_h : g_h2;

    for (int node = warpG; node < NN_NODES; node += nWarps) {
        int4 cb = *reinterpret_cast<const int4*>(&g_cntb[node * 4]);
        int4 cd = *reinterpret_cast<const int4*>(&g_cntd[node * 4]);
        float fb0 = (float)cb.x, fb1 = (float)cb.y, fb2 = (float)cb.z, fb3 = (float)cb.w;
        float fd0 = (float)cd.x, fd1 = (float)cd.y, fd2 = (float)cd.z;

        float acc[8];
        #pragma unroll
        for (int c = 0; c < 8; c++) {
            float v = base[c];
            v = fmaf(fb0, tB0[c], v);
            v = fmaf(fb1, tB1[c], v);
            v = fmaf(fb2, tB2[c], v);
            v = fmaf(fb3, tB3[c], v);
            v = fmaf(fd0, tD0[c], v);
            v = fmaf(fd1, tD1[c], v);
            v = fmaf(fd2, tD2[c], v);
            acc[c] = v;
        }

        {   // self row
            const float4* hrow = reinterpret_cast<const float4*>(H + (size_t)node * EMB + c0);
            float4 a0 = hrow[0], a1 = hrow[1];
            float raw[8] = {a0.x, a0.y, a0.z, a0.w, a1.x, a1.y, a1.z, a1.w};
            #pragma unroll
            for (int c = 0; c < 8; c++)
                acc[c] += (MODE == 0) ? raw[c] : fmaxf(fmaf(raw[c], sc[c], sh[c]), 0.f);
        }

        int s = g_off[node];
        int eEnd = s + g_indeg[node];
        int e = s;
        for (; e + 4 <= eEnd; e += 4) {
            int j0 = __ldg(&g_adj[e]);
            int j1 = __ldg(&g_adj[e + 1]);
            int j2 = __ldg(&g_adj[e + 2]);
            int j3 = __ldg(&g_adj[e + 3]);
            const float4* h0 = reinterpret_cast<const float4*>(H + (size_t)j0 * EMB + c0);
            const float4* h1 = reinterpret_cast<const float4*>(H + (size_t)j1 * EMB + c0);
            const float4* h2 = reinterpret_cast<const float4*>(H + (size_t)j2 * EMB + c0);
            const float4* h3 = reinterpret_cast<const float4*>(H + (size_t)j3 * EMB + c0);
            float4 a0 = h0[0], a1 = h0[1], b0 = h1[0], b1 = h1[1];
            float4 e0 = h2[0], e1 = h2[1], f0 = h3[0], f1 = h3[1];
            float r0[8] = {a0.x, a0.y, a0.z, a0.w, a1.x, a1.y, a1.z, a1.w};
            float r1[8] = {b0.x, b0.y, b0.z, b0.w, b1.x, b1.y, b1.z, b1.w};
            float r2[8] = {e0.x, e0.y, e0.z, e0.w, e1.x, e1.y, e1.z, e1.w};
            float r3[8] = {f0.x, f0.y, f0.z, f0.w, f1.x, f1.y, f1.z, f1.w};
            if (MODE == 0) {
                #pragma unroll
                for (int c = 0; c < 8; c++) acc[c] += (r0[c] + r1[c]) + (r2[c] + r3[c]);
            } else {
                #pragma unroll
                for (int c = 0; c < 8; c++) {
                    acc[c] += fmaxf(fmaf(r0[c], sc[c], sh[c]), 0.f);
                    acc[c] += fmaxf(fmaf(r1[c], sc[c], sh[c]), 0.f);
                    acc[c] += fmaxf(fmaf(r2[c], sc[c], sh[c]), 0.f);
                    acc[c] += fmaxf(fmaf(r3[c], sc[c], sh[c]), 0.f);
                }
            }
        }
        for (; e < eEnd; e++) {
            int j = __ldg(&g_adj[e]);
            const float4* hj = reinterpret_cast<const float4*>(H + (size_t)j * EMB + c0);
            float4 b0 = hj[0], b1 = hj[1];
            float raw[8] = {b0.x, b0.y, b0.z, b0.w, b1.x, b1.y, b1.z, b1.w};
            #pragma unroll
            for (int c = 0; c < 8; c++)
                acc[c] += (MODE == 0) ? raw[c] : fmaxf(fmaf(raw[c], sc[c], sh[c]), 0.f);
        }

        uint4 hv, lv;
        split_pair(acc[0], acc[1], hv.x, lv.x);
        split_pair(acc[2], acc[3], hv.y, lv.y);
        split_pair(acc[4], acc[5], hv.z, lv.z);
        split_pair(acc[6], acc[7], hv.w, lv.w);
        size_t obase = (size_t)node * (EMB / 2) + lane * 4;
        *reinterpret_cast<uint4*>(&g_aggH[obase]) = hv;
        *reinterpret_cast<uint4*>(&g_aggL[obase]) = lv;
    }
}

// ----------------------------------------------------------------------------
// Split-BF16 tensor-core GEMM: cp.async double-buffered (1 sync/tile),
// ldmatrix frags, 2 CTAs/SM. GRID IS TRANSPOSED: blockIdx.x = col tile,
// blockIdx.y = row tile, so a concurrent wave shares A row-slabs through L2.
//   D += Ahi*Bhi + Ahi*Blo + Alo*Bhi   (m16n8k16.bf16)
//   SEL=0: A=g_agg (K=256) -> g_hmid split + ReLU (NC=512); zeroes g_stats
//   SEL=1: A=g_hmid (K=512) -> g_h2 fp32 + BN stats (NC=256)
// ----------------------------------------------------------------------------
__device__ __forceinline__ void mma_bf16(float d[4], const uint32_t a[4], const uint32_t b[2]) {
    asm volatile(
        "mma.sync.aligned.m16n8k16.row.col.f32.bf16.bf16.f32 "
        "{%0,%1,%2,%3}, {%4,%5,%6,%7}, {%8,%9}, {%0,%1,%2,%3};"
        : "+f"(d[0]), "+f"(d[1]), "+f"(d[2]), "+f"(d[3])
        : "r"(a[0]), "r"(a[1]), "r"(a[2]), "r"(a[3]), "r"(b[0]), "r"(b[1]));
}

__device__ __forceinline__ void ldmx4(uint32_t* r, uint32_t addr) {
    asm volatile("ldmatrix.sync.aligned.m8n8.x4.shared.b16 {%0,%1,%2,%3}, [%4];"
                 : "=r"(r[0]), "=r"(r[1]), "=r"(r[2]), "=r"(r[3]) : "r"(addr));
}

__device__ __forceinline__ void cpa16(uint32_t dst, const void* src, int szbytes) {
    asm volatile("cp.async.cg.shared.global [%0], [%1], 16, %2;"
                 :: "r"(dst), "l"(src), "r"(szbytes));
}

template <int SEL>
__global__ void __launch_bounds__(256, 2)
gemm_tc_kernel(const float* __restrict__ bias, int layer) {
    constexpr int M = NN_NODES;
    constexpr int K = (SEL == 0) ? EMB : 2 * EMB;
    constexpr int NC = (SEL == 0) ? 2 * EMB : EMB;
    constexpr int KP = K / 2;
    const uint32_t* __restrict__ AH = (SEL == 0) ? g_aggH : g_hmidH;
    const uint32_t* __restrict__ AL = (SEL == 0) ? g_aggL : g_hmidL;
    const uint32_t* __restrict__ WH = ((SEL == 0) ? g_w1H : g_w2H) + (size_t)layer * NC * KP;
    const uint32_t* __restrict__ WL = ((SEL == 0) ? g_w1L : g_w2L) + (size_t)layer * NC * KP;

    constexpr int BM = 128, BN = 128;
    constexpr int BKP = 16;              // pairs per K-tile
    constexpr int LDU = BKP + 4;         // stride 20 u32: ldmatrix conflict-free
    constexpr int AR = BM * LDU;         // 2560 u32 per array
    constexpr int STG = 4 * AR;          // u32 per stage
    constexpr int NT = KP / BKP;         // K tiles

    extern __shared__ uint32_t dsm[];
    __shared__ float sSum[BN];
    __shared__ float sSq[BN];
    uint32_t sbase = (uint32_t)__cvta_generic_to_shared(dsm);

    int tid = threadIdx.x;
    int wid = tid >> 5, lane = tid & 31;
    int wm = wid & 1;
    int wn = wid >> 1;
    int rowBase = blockIdx.y * BM;      // TRANSPOSED GRID
    int colBase = blockIdx.x * BN;

    if (SEL == 1 && tid < BN) { sSum[tid] = 0.f; sSq[tid] = 0.f; }
    if (SEL == 0 && blockIdx.x == 0 && blockIdx.y == 0 && tid < 256) {
        g_stats[tid] = 0.f;
        g_stats[256 + tid] = 0.f;
    }

    float d[4][4][4];
    #pragma unroll
    for (int i = 0; i < 4; i++)
        #pragma unroll
        for (int j = 0; j < 4; j++)
            #pragma unroll
            for (int r = 0; r < 4; r++) d[i][j][r] = 0.0f;

    int gid = lane >> 2;
    int tig = lane & 3;

    int srow0 = tid >> 2;
    int sfq0 = tid & 3;
    int srow1 = (tid + 256) >> 2;

    int aRow = wm * 64 + (lane & 15);
    int aCol = (lane >> 4) * 4;
    int bRow = wn * 32 + (lane & 7) + ((lane >> 4) << 3);
    int bCol = ((lane >> 3) & 1) * 4;

    auto prefetch = [&](int t, int s) {
        int kp0 = t * BKP;
        uint32_t sb = sbase + (uint32_t)(s * STG) * 4;
        #pragma unroll
        for (int r = 0; r < 2; r++) {
            int row = (r == 0) ? srow0 : srow1;
            uint32_t doff = (uint32_t)(row * LDU + sfq0 * 4) * 4;
            int grow = rowBase + row;
            size_t ab = (size_t)grow * KP + kp0 + sfq0 * 4;
            int sz = (grow < M) ? 16 : 0;
            cpa16(sb + 0 * AR * 4 + doff, AH + ab, sz);
            cpa16(sb + 1 * AR * 4 + doff, AL + ab, sz);
            size_t bb = (size_t)(colBase + row) * KP + kp0 + sfq0 * 4;
            cpa16(sb + 2 * AR * 4 + doff, WH + bb, 16);
            cpa16(sb + 3 * AR * 4 + doff, WL + bb, 16);
        }
        asm volatile("cp.async.commit_group;");
    };

    prefetch(0, 0);

    for (int t = 0; t < NT; t++) {
        int s = t & 1;
        asm volatile("cp.async.wait_group 0;");
        __syncthreads();
        if (t + 1 < NT) prefetch(t + 1, 1 - s);

        uint32_t aH_b = sbase + (uint32_t)(s * STG + 0 * AR) * 4;
        uint32_t aL_b = sbase + (uint32_t)(s * STG + 1 * AR) * 4;
        uint32_t bH_b = sbase + (uint32_t)(s * STG + 2 * AR) * 4;
        uint32_t bL_b = sbase + (uint32_t)(s * STG + 3 * AR) * 4;

        #pragma unroll
        for (int ks = 0; ks < 2; ks++) {
            int base = ks * 8;
            uint32_t bh[4][2], bl[4][2];
            #pragma unroll
            for (int nfp = 0; nfp < 2; nfp++) {
                uint32_t off = ((uint32_t)(bRow + nfp * 16) * LDU + base + bCol) * 4;
                uint32_t rh[4], rl[4];
                ldmx4(rh, bH_b + off);
                ldmx4(rl, bL_b + off);
                bh[2 * nfp][0] = rh[0]; bh[2 * nfp][1] = rh[1];
                bh[2 * nfp + 1][0] = rh[2]; bh[2 * nfp + 1][1] = rh[3];
                bl[2 * nfp][0] = rl[0]; bl[2 * nfp][1] = rl[1];
                bl[2 * nfp + 1][0] = rl[2]; bl[2 * nfp + 1][1] = rl[3];
            }
            #pragma unroll
            for (int mf = 0; mf < 4; mf++) {
                uint32_t off = ((uint32_t)(aRow + mf * 16) * LDU + base + aCol) * 4;
                uint32_t ah[4], al[4];
                ldmx4(ah, aH_b + off);
                ldmx4(al, aL_b + off);
                #pragma unroll
                for (int nf = 0; nf < 4; nf++) {
                    mma_bf16(d[mf][nf], ah, bh[nf]);   // hi*hi
                    mma_bf16(d[mf][nf], ah, bl[nf]);   // hi*lo
                    mma_bf16(d[mf][nf], al, bh[nf]);   // lo*hi
                }
            }
        }
        __syncthreads();
    }

    // --- epilogue ---
    #pragma unroll
    for (int nf = 0; nf < 4; nf++) {
        int col = colBase + wn * 32 + nf * 8 + tig * 2;
        int lcol = wn * 32 + nf * 8 + tig * 2;
        float b0 = __ldg(&bias[col]);
        float b1 = __ldg(&bias[col + 1]);
        float s0 = 0.f, q0 = 0.f, s1 = 0.f, q1 = 0.f;
        #pragma unroll
        for (int mf = 0; mf < 4; mf++) {
            int row = rowBase + wm * 64 + mf * 16 + gid;
            if (row < M) {
                float v0 = d[mf][nf][0] + b0;
                float v1 = d[mf][nf][1] + b1;
                if (SEL == 0) {
                    v0 = fmaxf(v0, 0.f); v1 = fmaxf(v1, 0.f);
                    uint32_t hi, lo;
                    split_pair(v0, v1, hi, lo);
                    size_t p = (size_t)row * (NC / 2) + (col >> 1);
                    g_hmidH[p] = hi; g_hmidL[p] = lo;
                } else {
                    g_h2[(size_t)row * NC + col] = v0;
                    g_h2[(size_t)row * NC + col + 1] = v1;
                    s0 += v0; q0 += v0 * v0; s1 += v1; q1 += v1 * v1;
                }
            }
            if (row + 8 < M) {
                float v2 = d[mf][nf][2] + b0;
                float v3 = d[mf][nf][3] + b1;
                if (SEL == 0) {
                    v2 = fmaxf(v2, 0.f); v3 = fmaxf(v3, 0.f);
                    uint32_t hi, lo;
                    split_pair(v2, v3, hi, lo);
                    size_t p = (size_t)(row + 8) * (NC / 2) + (col >> 1);
                    g_hmidH[p] = hi; g_hmidL[p] = lo;
                } else {
                    g_h2[(size_t)(row + 8) * NC + col] = v2;
                    g_h2[(size_t)(row + 8) * NC + col + 1] = v3;
                    s0 += v2; q0 += v2 * v2; s1 += v3; q1 += v3 * v3;
                }
            }
        }
        if (SEL == 1) {
            atomicAdd(&sSum[lcol], s0); atomicAdd(&sSq[lcol], q0);
            atomicAdd(&sSum[lcol + 1], s1); atomicAdd(&sSq[lcol + 1], q1);
        }
    }
    if (SEL == 1) {
        __syncthreads();
        if (tid < BN) {
            atomicAdd(&g_stats[colBase + tid], sSum[tid]);
            atomicAdd(&g_stats[EMB + colBase + tid], sSq[tid]);
        }
    }
}

// ----------------------------------------------------------------------------
// Final output: out = h2 * scale + shift (no relu); scale/shift from stats.
// ----------------------------------------------------------------------------
__global__ void bn_apply_kernel(float* __restrict__ out_ext,
                                const float* __restrict__ bnw,
                                const float* __restrict__ bnb) {
    int t = blockIdx.x * blockDim.x + threadIdx.x;
    if (t >= NN_NODES * (EMB / 4)) return;
    int q = t & 63;
    int c0 = q * 4;
    float invN = 1.0f / (float)NN_NODES;
    float4 v = reinterpret_cast<const float4*>(g_h2)[t];
    float o[4];
    float vv[4] = {v.x, v.y, v.z, v.w};
    #pragma unroll
    for (int c = 0; c < 4; c++) {
        int cc = c0 + c;
        float mean = g_stats[cc] * invN;
        float var = g_stats[EMB + cc] * invN - mean * mean;
        float s = __ldg(&bnw[cc]) * rsqrtf(var + BN_EPS);
        o[c] = fmaf(vv[c], s, __ldg(&bnb[cc]) - mean * s);
    }
    reinterpret_cast<float4*>(out_ext)[t] = make_float4(o[0], o[1], o[2], o[3]);
}

// ----------------------------------------------------------------------------
extern "C" void kernel_launch(void* const* d_in, const int* in_sizes, int n_in,
                              void* d_out, int out_size) {
    const int*   x_atom    = (const int*)d_in[0];
    const int*   x_chir    = (const int*)d_in[1];
    const int*   edge_idx  = (const int*)d_in[2];    // [2,E]
    const int*   edge_bond = (const int*)d_in[3];
    const int*   edge_dir  = (const int*)d_in[4];
    const float* atom_emb  = (const float*)d_in[5];  // [120,256]
    const float* chir_emb  = (const float*)d_in[6];  // [3,256]
    const float* bond_embs = (const float*)d_in[7];  // [5,6,256]
    const float* dir_embs  = (const float*)d_in[8];  // [5,3,256]
    const float* W1s       = (const float*)d_in[9];  // [5,512,256]
    const float* b1s       = (const float*)d_in[10]; // [5,512]
    const float* W2s       = (const float*)d_in[11]; // [5,256,512]
    const float* b2s       = (const float*)d_in[12]; // [5,256]
    const float* bn_w      = (const float*)d_in[13]; // [5,256]
    const float* bn_b      = (const float*)d_in[14]; // [5,256]
    float* out = (float*)d_out;

    const int* src = edge_idx;
    const int* dst = edge_idx + EE_EDGES;

    const int SMEM_GEMM = 2 * 4 * 128 * 20 * 4;   // 81920 B
    cudaFuncSetAttribute(gemm_tc_kernel<0>, cudaFuncAttributeMaxDynamicSharedMemorySize, SMEM_GEMM);
    cudaFuncSetAttribute(gemm_tc_kernel<1>, cudaFuncAttributeMaxDynamicSharedMemorySize, SMEM_GEMM);

    // --- preprocessing ---
    zero_scratch_kernel<<<512, 256>>>();
    hist_kernel<<<cdiv(EE_EDGES, 256), 256>>>(src, dst, edge_bond, edge_dir);
    offsets_kernel<<<cdiv(NN_NODES, 256), 256>>>();
    fill_kernel<<<cdiv(EE_EDGES, 256), 256>>>(src, dst);
    init_h_kernel<<<cdiv(NN_NODES * (EMB / 4), 256), 256>>>(x_atom, x_chir, atom_emb, chir_emb);
    split_w_kernel<<<cdiv(2 * NUM_LAYER * 512 * 128, 256), 256>>>(W1s, W2s);

    // TRANSPOSED GRIDS: x = col tiles, y = row tiles (A reuse through L2)
    dim3 g1(2 * EMB / 128, cdiv(NN_NODES, 128));  // 4 x 782
    dim3 g2(EMB / 128, cdiv(NN_NODES, 128));      // 2 x 782
    const int aggBlocks = 592;                    // grid-stride: 4736 warps
    int applyBlocks = cdiv(NN_NODES * (EMB / 4), 256);

    for (int l = 0; l < NUM_LAYER; l++) {
        const float* BE = bond_embs + (size_t)l * 6 * EMB;
        const float* DE = dir_embs + (size_t)l * 3 * EMB;
        const float* B1 = b1s + (size_t)l * 2 * EMB;
        const float* B2 = b2s + (size_t)l * EMB;

        if (l == 0) agg_kernel<0><<<aggBlocks, 256>>>(BE, DE, nullptr, nullptr);
        else        agg_kernel<1><<<aggBlocks, 256>>>(BE, DE,
                        bn_w + (size_t)(l - 1) * EMB, bn_b + (size_t)(l - 1) * EMB);
        gemm_tc_kernel<0><<<g1, 256, SMEM_GEMM>>>(B1, l);   // hmid = relu(agg@W1^T+b1)
        gemm_tc_kernel<1><<<g2, 256, SMEM_GEMM>>>(B2, l);   // h2 = hmid@W2^T+b2 (+stats)
    }
    bn_apply_kernel<<<applyBlocks, 256>>>(out,
        bn_w + (size_t)(NUM_LAYER - 1) * EMB, bn_b + (size_t)(NUM_LAYER - 1) * EMB);
}